// round 1
// baseline (speedup 1.0000x reference)
#include <cuda_runtime.h>
#include <math.h>

#define B    128
#define C1   16
#define L0   719
#define L1   688     // conv1 out
#define L2   343     // pool(3,2)
#define L3   171     // miu pool out / x_miu length
#define CM   32      // x_miu channels
#define AE1C 64
#define L4   85      // h1 length
#define AE2C 32
#define L5   42      // h2 length
#define L7   86      // h3 length (up 84 + pad4 - 3 + 1)
#define AE4C 32
#define L9   174     // h4 length (up 172 + pad4 - 3 + 1)
#define CI   160     // inp channels (K_SEG*32)
#define LI   171     // inp length
#define LU   170     // until / logic length
#define C_X1 200
#define EPSL 1e-6f

// ---------------- scratch (device globals; no allocs allowed) ----------------
__device__ float g_conv1[B*C1*L1];
__device__ float g_bn_scale[C1];
__device__ float g_bn_shift[C1];
__device__ float g_xf[B*C1*L2];
__device__ float g_xmiu[B*CM*L3];
__device__ float g_h1[B*AE1C*L4];
__device__ float g_h2[B*AE2C*L5];
__device__ float g_h3[B*AE1C*L7];
__device__ float g_h4[B*AE4C*L9];
__device__ float g_inp[B*CI*LI];
__device__ float g_logp[B*CI*LI];
__device__ float g_logq[B*CI*LI];
__device__ float g_x1[B*C_X1*LU];
__device__ float g_logp1[B*C_X1*LU];
__device__ float g_logq1[B*C_X1*LU];
__device__ float g_x2[B*12*LU];
__device__ float g_fc1o[B*12*1024];
__device__ float g_fc2o[B*12*256];
__device__ float g_wn_and2[20*CI*2];
__device__ float g_wn_or2 [20*CI*2];
__device__ float g_wn_and [6*C_X1*2];
__device__ float g_wn_or  [6*C_X1*2];

static inline int cdiv(int a, int b) { return (a + b - 1) / b; }

__device__ __forceinline__ float sigf(float z) { return 1.0f / (1.0f + expf(-z)); }

// jax.image.resize linear, factor 2 (derived from the weight matrix:
// out[0]=in[0]; out[2j]=0.25 in[j-1]+0.75 in[j]; out[2j+1]=0.75 in[j]+0.25 in[j+1]; out[2L-1]=in[L-1])
__device__ __forceinline__ float up2(const float* in, int L, int p) {
    int j = p >> 1;
    if (p & 1) {
        float a = in[j];
        float b = (j + 1 < L) ? in[j + 1] : in[j];
        return 0.75f * a + 0.25f * b;
    } else {
        float a = (j - 1 >= 0) ? in[j - 1] : in[j];
        float b = in[j];
        return 0.25f * a + 0.75f * b;
    }
}

// ---------------- stage kernels ----------------

__global__ void k_conv1(const float* __restrict__ x, const float* __restrict__ w) {
    int idx = blockIdx.x * blockDim.x + threadIdx.x;
    if (idx >= B * C1 * L1) return;
    int t = idx % L1;
    int o = (idx / L1) % C1;
    int b = idx / (L1 * C1);
    const float* xr = x + b * L0 + t;
    const float* wr = w + o * 32;
    float s = 0.f;
#pragma unroll
    for (int k = 0; k < 32; k++) s = fmaf(__ldg(xr + k), __ldg(wr + k), s);
    g_conv1[idx] = s;
}

__global__ void k_bnstats(const float* __restrict__ gg, const float* __restrict__ bb) {
    int c = blockIdx.x;
    int tid = threadIdx.x;
    double s = 0.0, s2 = 0.0;
    for (int i = tid; i < B * L1; i += 256) {
        int b = i / L1, t = i % L1;
        float v = g_conv1[(b * C1 + c) * L1 + t];
        s += (double)v;
        s2 += (double)v * (double)v;
    }
    __shared__ double sh[256], sh2[256];
    sh[tid] = s; sh2[tid] = s2;
    __syncthreads();
    for (int st = 128; st > 0; st >>= 1) {
        if (tid < st) { sh[tid] += sh[tid + st]; sh2[tid] += sh2[tid + st]; }
        __syncthreads();
    }
    if (tid == 0) {
        double n = (double)(B * L1);
        double mean = sh[0] / n;
        double var = sh2[0] / n - mean * mean;
        float inv = rsqrtf((float)var + 1e-5f);
        float sc = gg[c] * inv;
        g_bn_scale[c] = sc;
        g_bn_shift[c] = bb[c] - (float)mean * sc;
    }
}

__global__ void k_bnpool() {
    int idx = blockIdx.x * blockDim.x + threadIdx.x;
    if (idx >= B * C1 * L2) return;
    int l = idx % L2;
    int c = (idx / L2) % C1;
    int b = idx / (L2 * C1);
    const float* row = &g_conv1[(b * C1 + c) * L1 + 2 * l];
    float sc = g_bn_scale[c], sh = g_bn_shift[c];
    float m = -INFINITY;
#pragma unroll
    for (int i = 0; i < 3; i++) m = fmaxf(m, fmaxf(0.f, row[i] * sc + sh));
    g_xf[idx] = m;
}

__global__ void k_miu(const float* __restrict__ ap, const float* __restrict__ bp,
                      const float* __restrict__ an, const float* __restrict__ bn) {
    int idx = blockIdx.x * blockDim.x + threadIdx.x;
    if (idx >= B * C1 * L3) return;
    int l = idx % L3;
    int c = (idx / L3) % C1;
    int b = idx / (L3 * C1);
    const float* row = &g_xf[(b * C1 + c) * L2 + 2 * l];
    float a_p = ap[c], b_p = bp[c], a_n = an[c], b_n = bn[c];
    float mp = -INFINITY, mn = -INFINITY;
#pragma unroll
    for (int i = 0; i < 3; i++) {
        float v = row[i];
        mp = fmaxf(mp, sigf(a_p * (v - b_p)));
        mn = fmaxf(mn, sigf(-a_n * (v - b_n)));
    }
    g_xmiu[(b * CM + c) * L3 + l] = mp;
    g_xmiu[(b * CM + 16 + c) * L3 + l] = mn;
}

// conv(pad1,k3)+tanh+pool(3,2): x_miu(32,171) -> h1(64,85)
__global__ void k_ae1(const float* __restrict__ w1, const float* __restrict__ b1) {
    int idx = blockIdx.x * blockDim.x + threadIdx.x;
    if (idx >= B * AE1C * L4) return;
    int l = idx % L4;
    int oc = (idx / L4) % AE1C;
    int b = idx / (L4 * AE1C);
    float m = -INFINITY;
#pragma unroll
    for (int i = 0; i < 3; i++) {
        int p = 2 * l + i;
        float s = b1[oc];
        bool lv = (p - 1 >= 0), rv = (p + 1 < L3);
        for (int ic = 0; ic < CM; ic++) {
            const float* xr = &g_xmiu[(b * CM + ic) * L3];
            const float* wr = &w1[(oc * CM + ic) * 3];
            float s0 = lv ? xr[p - 1] : 0.f;
            float s2 = rv ? xr[p + 1] : 0.f;
            s = fmaf(s0, __ldg(wr + 0), s);
            s = fmaf(xr[p], __ldg(wr + 1), s);
            s = fmaf(s2, __ldg(wr + 2), s);
        }
        m = fmaxf(m, tanhf(s));
    }
    g_h1[idx] = m;
}

// conv(pad1,k3)+relu+pool(3,2): h1(64,85) -> h2(32,42)
__global__ void k_ae2(const float* __restrict__ w2, const float* __restrict__ b2) {
    int idx = blockIdx.x * blockDim.x + threadIdx.x;
    if (idx >= B * AE2C * L5) return;
    int l = idx % L5;
    int oc = (idx / L5) % AE2C;
    int b = idx / (L5 * AE2C);
    float m = -INFINITY;
#pragma unroll
    for (int i = 0; i < 3; i++) {
        int p = 2 * l + i;
        float s = b2[oc];
        bool lv = (p - 1 >= 0), rv = (p + 1 < L4);
        for (int ic = 0; ic < AE1C; ic++) {
            const float* xr = &g_h1[(b * AE1C + ic) * L4];
            const float* wr = &w2[(oc * AE1C + ic) * 3];
            float s0 = lv ? xr[p - 1] : 0.f;
            float s2 = rv ? xr[p + 1] : 0.f;
            s = fmaf(s0, __ldg(wr + 0), s);
            s = fmaf(xr[p], __ldg(wr + 1), s);
            s = fmaf(s2, __ldg(wr + 2), s);
        }
        m = fmaxf(m, fmaxf(0.f, s));
    }
    g_h2[idx] = m;
}

// upsample2(h2) -> conv(pad2,k3)+tanh: -> h3(64,86)
__global__ void k_ae3(const float* __restrict__ w3, const float* __restrict__ b3) {
    int idx = blockIdx.x * blockDim.x + threadIdx.x;
    if (idx >= B * AE1C * L7) return;
    int t = idx % L7;
    int oc = (idx / L7) % AE1C;
    int b = idx / (L7 * AE1C);
    float s = b3[oc];
    for (int ic = 0; ic < AE2C; ic++) {
        const float* h2r = &g_h2[(b * AE2C + ic) * L5];
        const float* wr = &w3[(oc * AE2C + ic) * 3];
#pragma unroll
        for (int kw = 0; kw < 3; kw++) {
            int p = t - 2 + kw;
            if (p >= 0 && p < 2 * L5) s = fmaf(up2(h2r, L5, p), __ldg(wr + kw), s);
        }
    }
    g_h3[idx] = tanhf(s);
}

// upsample2(h3) -> conv(pad2,k3)+sigmoid: -> h4(32,174)
__global__ void k_ae4(const float* __restrict__ w4, const float* __restrict__ b4) {
    int idx = blockIdx.x * blockDim.x + threadIdx.x;
    if (idx >= B * AE4C * L9) return;
    int t = idx % L9;
    int oc = (idx / L9) % AE4C;
    int b = idx / (L9 * AE4C);
    float s = b4[oc];
    for (int ic = 0; ic < AE1C; ic++) {
        const float* h3r = &g_h3[(b * AE1C + ic) * L7];
        const float* wr = &w4[(oc * AE1C + ic) * 3];
#pragma unroll
        for (int kw = 0; kw < 3; kw++) {
            int p = t - 2 + kw;
            if (p >= 0 && p < 2 * L7) s = fmaf(up2(h3r, L7, p), __ldg(wr + kw), s);
        }
    }
    g_h4[idx] = sigf(s);
}

// maxpool(4,1) over h4 + segmentation mask -> inp(160,171)
__global__ void k_seg() {
    int idx = blockIdx.x * blockDim.x + threadIdx.x;
    if (idx >= B * CM * L3) return;
    int l = idx % L3;
    int c = (idx / L3) % CM;
    int b = idx / (L3 * CM);
    const float* h4r = &g_h4[(b * AE4C + c) * L9 + l];
    float wv = fmaxf(fmaxf(h4r[0], h4r[1]), fmaxf(h4r[2], h4r[3]));
    float xm = g_xmiu[(b * CM + c) * L3 + l];
    float prod = wv * xm;
#pragma unroll
    for (int k = 0; k < 5; k++) {
        float lo = (float)k / 5.0f;
        float hi = (k == 4) ? 2.0f : (float)(k + 1) / 5.0f;
        bool on = (wv >= lo) && (wv < hi);
        g_inp[(b * CI + k * 32 + c) * LI + l] = on ? prod : 0.f;
    }
}

// logs for logic layer 1 + until (== max(0, min(x[t], x[t+1])))
__global__ void k_until_logs() {
    int idx = blockIdx.x * blockDim.x + threadIdx.x;
    if (idx >= B * CI * LI) return;
    int l = idx % LI;
    int c = (idx / LI) % CI;
    int b = idx / (LI * CI);
    float v = g_inp[idx];
    float cv = fminf(fmaxf(v, 0.f), 1.f);
    g_logp[idx] = logf(cv + EPSL);
    g_logq[idx] = logf(1.0f - cv + EPSL);
    if (l < LU) {
        float v2 = g_inp[idx + 1];
        g_x1[(b * C_X1 + 40 + c) * LU + l] = fmaxf(0.f, fminf(v, v2));
    }
}

// softmax over flattened (in_ch*kw) per out-channel
__global__ void k_softmax_w(const float* __restrict__ w, float* __restrict__ out, int sz) {
    int o = blockIdx.x;
    int tid = threadIdx.x;
    const float* row = w + o * sz;
    __shared__ float red[64];
    float mx = -INFINITY;
    for (int i = tid; i < sz; i += 64) mx = fmaxf(mx, row[i]);
    red[tid] = mx; __syncthreads();
    for (int s = 32; s > 0; s >>= 1) { if (tid < s) red[tid] = fmaxf(red[tid], red[tid + s]); __syncthreads(); }
    mx = red[0]; __syncthreads();
    float sm = 0.f;
    for (int i = tid; i < sz; i += 64) sm += expf(row[i] - mx);
    red[tid] = sm; __syncthreads();
    for (int s = 32; s > 0; s >>= 1) { if (tid < s) red[tid] += red[tid + s]; __syncthreads(); }
    sm = red[0];
    for (int i = tid; i < sz; i += 64) out[o * sz + i] = expf(row[i] - mx) / sm;
}

// logic layer 1: and/or conv (k=2, no pad) over logp/logq -> x1 channels 0..39
__global__ void k_logic1() {
    int idx = blockIdx.x * blockDim.x + threadIdx.x;
    if (idx >= B * 20 * LU) return;
    int t = idx % LU;
    int o = (idx / LU) % 20;
    int b = idx / (LU * 20);
    const float* wa = &g_wn_and2[o * CI * 2];
    const float* wo = &g_wn_or2[o * CI * 2];
    float sa = 0.f, so = 0.f;
    for (int c = 0; c < CI; c++) {
        int base = (b * CI + c) * LI + t;
        float p0 = g_logp[base], p1 = g_logp[base + 1];
        float q0 = g_logq[base], q1 = g_logq[base + 1];
        sa = fmaf(__ldg(wa + 2 * c), p0, sa);
        sa = fmaf(__ldg(wa + 2 * c + 1), p1, sa);
        so = fmaf(__ldg(wo + 2 * c), q0, so);
        so = fmaf(__ldg(wo + 2 * c + 1), q1, so);
    }
    g_x1[(b * C_X1 + o) * LU + t] = fmaxf(0.f, expf(sa));
    g_x1[(b * C_X1 + 20 + o) * LU + t] = fmaxf(0.f, 1.0f - expf(so));
}

__global__ void k_logs1() {
    int idx = blockIdx.x * blockDim.x + threadIdx.x;
    if (idx >= B * C_X1 * LU) return;
    float v = g_x1[idx];
    float cv = fminf(fmaxf(v, 0.f), 1.f);
    g_logp1[idx] = logf(cv + EPSL);
    g_logq1[idx] = logf(1.0f - cv + EPSL);
}

// logic layer 2: and/or conv (k=2, pad left 1 in LOG domain with zeros) -> x2(12,170)
__global__ void k_logic2() {
    int idx = blockIdx.x * blockDim.x + threadIdx.x;
    if (idx >= B * 6 * LU) return;
    int t = idx % LU;
    int o = (idx / LU) % 6;
    int b = idx / (LU * 6);
    const float* wa = &g_wn_and[o * C_X1 * 2];
    const float* wo = &g_wn_or[o * C_X1 * 2];
    float sa = 0.f, so = 0.f;
    bool hasL = (t > 0);
    for (int c = 0; c < C_X1; c++) {
        int base = (b * C_X1 + c) * LU + t;
        float p1 = g_logp1[base];
        float q1 = g_logq1[base];
        float p0 = hasL ? g_logp1[base - 1] : 0.f;
        float q0 = hasL ? g_logq1[base - 1] : 0.f;
        sa = fmaf(__ldg(wa + 2 * c), p0, sa);
        sa = fmaf(__ldg(wa + 2 * c + 1), p1, sa);
        so = fmaf(__ldg(wo + 2 * c), q0, so);
        so = fmaf(__ldg(wo + 2 * c + 1), q1, so);
    }
    g_x2[(b * 12 + o) * LU + t] = fmaxf(0.f, expf(sa));
    g_x2[(b * 12 + 6 + o) * LU + t] = fmaxf(0.f, 1.0f - expf(so));
}

// C[M,N] = act(A[M,K] @ W[N,K]^T + bias[N]); 16x16 tiled
__global__ void k_gemm(const float* __restrict__ A, const float* __restrict__ W,
                       const float* __restrict__ bias, float* __restrict__ C,
                       int M, int N, int K, int relu) {
    __shared__ float As[16][16];
    __shared__ float Ws[16][17];  // Ws[k_local][n_local]
    int ty = threadIdx.y, tx = threadIdx.x;
    int row = blockIdx.y * 16 + ty;
    int col = blockIdx.x * 16 + tx;
    float acc = 0.f;
    for (int k0 = 0; k0 < K; k0 += 16) {
        int ka = k0 + tx;
        As[ty][tx] = (row < M && ka < K) ? A[row * K + ka] : 0.f;
        int n = blockIdx.x * 16 + ty;
        int kb = k0 + tx;
        Ws[tx][ty] = (n < N && kb < K) ? W[n * K + kb] : 0.f;
        __syncthreads();
#pragma unroll
        for (int kk = 0; kk < 16; kk++) acc = fmaf(As[ty][kk], Ws[kk][tx], acc);
        __syncthreads();
    }
    if (row < M && col < N) {
        acc += bias[col];
        if (relu) acc = fmaxf(acc, 0.f);
        C[row * N + col] = acc;
    }
}

// ---------------- launcher ----------------

extern "C" void kernel_launch(void* const* d_in, const int* in_sizes, int n_in,
                              void* d_out, int out_size) {
    const float* x      = (const float*)d_in[0];
    const float* wave_w = (const float*)d_in[1];
    const float* bn_g   = (const float*)d_in[2];
    const float* bn_b   = (const float*)d_in[3];
    const float* miu_ap = (const float*)d_in[4];
    const float* miu_bp = (const float*)d_in[5];
    const float* miu_an = (const float*)d_in[6];
    const float* miu_bn = (const float*)d_in[7];
    const float* ae_w1  = (const float*)d_in[8];
    const float* ae_b1  = (const float*)d_in[9];
    const float* ae_w2  = (const float*)d_in[10];
    const float* ae_b2  = (const float*)d_in[11];
    const float* ae_w3  = (const float*)d_in[12];
    const float* ae_b3  = (const float*)d_in[13];
    const float* ae_w4  = (const float*)d_in[14];
    const float* ae_b4  = (const float*)d_in[15];
    const float* and2_w = (const float*)d_in[16];
    const float* or2_w  = (const float*)d_in[17];
    const float* and_w  = (const float*)d_in[18];
    const float* or_w   = (const float*)d_in[19];
    const float* fc1_w  = (const float*)d_in[20];
    const float* fc1_b  = (const float*)d_in[21];
    const float* fc2_w  = (const float*)d_in[22];
    const float* fc2_b  = (const float*)d_in[23];
    const float* fc3_w  = (const float*)d_in[24];
    const float* fc3_b  = (const float*)d_in[25];
    float* out = (float*)d_out;

    const int T = 256;

    k_conv1<<<cdiv(B * C1 * L1, T), T>>>(x, wave_w);
    k_bnstats<<<C1, 256>>>(bn_g, bn_b);
    k_bnpool<<<cdiv(B * C1 * L2, T), T>>>();
    k_miu<<<cdiv(B * C1 * L3, T), T>>>(miu_ap, miu_bp, miu_an, miu_bn);
    k_ae1<<<cdiv(B * AE1C * L4, T), T>>>(ae_w1, ae_b1);
    k_ae2<<<cdiv(B * AE2C * L5, T), T>>>(ae_w2, ae_b2);
    k_ae3<<<cdiv(B * AE1C * L7, T), T>>>(ae_w3, ae_b3);
    k_ae4<<<cdiv(B * AE4C * L9, T), T>>>(ae_w4, ae_b4);
    k_seg<<<cdiv(B * CM * L3, T), T>>>();
    k_until_logs<<<cdiv(B * CI * LI, T), T>>>();

    {
        float* p;
        cudaGetSymbolAddress((void**)&p, g_wn_and2);
        k_softmax_w<<<20, 64>>>(and2_w, p, CI * 2);
        cudaGetSymbolAddress((void**)&p, g_wn_or2);
        k_softmax_w<<<20, 64>>>(or2_w, p, CI * 2);
        cudaGetSymbolAddress((void**)&p, g_wn_and);
        k_softmax_w<<<6, 64>>>(and_w, p, C_X1 * 2);
        cudaGetSymbolAddress((void**)&p, g_wn_or);
        k_softmax_w<<<6, 64>>>(or_w, p, C_X1 * 2);
    }

    k_logic1<<<cdiv(B * 20 * LU, T), T>>>();
    k_logs1<<<cdiv(B * C_X1 * LU, T), T>>>();
    k_logic2<<<cdiv(B * 6 * LU, T), T>>>();

    float *pa, *pb, *pc;
    cudaGetSymbolAddress((void**)&pa, g_x2);
    cudaGetSymbolAddress((void**)&pb, g_fc1o);
    cudaGetSymbolAddress((void**)&pc, g_fc2o);

    dim3 bt(16, 16);
    {
        dim3 gr(cdiv(1024, 16), cdiv(B * 12, 16));
        k_gemm<<<gr, bt>>>(pa, fc1_w, fc1_b, pb, B * 12, 1024, LU, 1);
    }
    {
        dim3 gr(cdiv(256, 16), cdiv(B * 12, 16));
        k_gemm<<<gr, bt>>>(pb, fc2_w, fc2_b, pc, B * 12, 256, 1024, 1);
    }
    {
        dim3 gr(cdiv(10, 16), cdiv(B * 12, 16));
        k_gemm<<<gr, bt>>>(pc, fc3_w, fc3_b, out, B * 12, 10, 256, 0);
    }
    (void)in_sizes; (void)n_in; (void)out_size;
}

// round 2
// speedup vs baseline: 1.9358x; 1.9358x over previous
#include <cuda_runtime.h>
#include <math.h>

#define B    128
#define C1   16
#define L0   719
#define L1   688
#define L2   343
#define L3   171     // x_miu length
#define CM   32
#define L4   85      // h1 length (pool of 171)
#define L5   42      // h2 length
#define L7   86      // h3 length
#define L9   174     // h4 length
#define CI   160
#define LI   171
#define LU   170
#define C_X1 200
#define EPSL 1e-6f

// ---------------- scratch ----------------
__device__ float g_conv1[B*C1*L1];
__device__ double g_bns[C1*8*2];
__device__ float g_bn_scale[C1];
__device__ float g_bn_shift[C1];
__device__ float g_xf[B*C1*L2];
__device__ float g_xmiu[B*CM*L3];          // channel-first [b][32][171]
__device__ float g_A1[B*L3*96];            // im2col ae1
__device__ float g_T1[B*L3*64];            // conv1 out (tanh), channel-last
__device__ float g_h1[B*L4*64];            // channel-last
__device__ float g_A2[B*L4*192];
__device__ float g_T2[B*L4*32];
__device__ float g_h2[B*L5*32];            // channel-last
__device__ float g_A3[B*L7*96];
__device__ float g_h3[B*L7*64];            // channel-last
__device__ float g_A4[B*L9*192];
__device__ float g_h4[B*L9*32];            // channel-last
__device__ float g_inp[B*CI*LI];           // channel-first
__device__ float g_logp[B*CI*LI];
__device__ float g_logq[B*CI*LI];
__device__ float g_x1[B*C_X1*LU];          // channel-first
__device__ float g_logp1[B*C_X1*LU];
__device__ float g_logq1[B*C_X1*LU];
__device__ float g_x2[B*12*LU];
__device__ float g_fc1o[B*12*1024];
__device__ float g_fc2o[B*12*256];
__device__ float g_wn_and2[20*CI*2];
__device__ float g_wn_or2 [20*CI*2];
__device__ float g_wn_and [6*C_X1*2];
__device__ float g_wn_or  [6*C_X1*2];

static inline int cdiv(int a, int b) { return (a + b - 1) / b; }

__device__ __forceinline__ float sigfast(float z) {
    return __fdividef(1.0f, 1.0f + __expf(-z));
}

// jax.image.resize linear x2 gather, channel-last layout (stride between time steps)
__device__ __forceinline__ float up2cl(const float* base, int stride, int L, int p) {
    int j = p >> 1;
    if (p & 1) {
        float a = base[j * stride];
        float b2 = base[((j + 1 < L) ? (j + 1) : j) * stride];
        return 0.75f * a + 0.25f * b2;
    } else {
        float a = base[((j > 0) ? (j - 1) : 0) * stride];
        float b2 = base[j * stride];
        return 0.25f * a + 0.75f * b2;
    }
}

// ---------------- front-end ----------------

// conv1: 4 outputs per thread, sliding window (16 LDG per output instead of 64)
__global__ void k_conv1(const float* __restrict__ x, const float* __restrict__ w) {
    int idx = blockIdx.x * blockDim.x + threadIdx.x;
    const int G = L1 / 4;  // 172
    if (idx >= B * C1 * G) return;
    int g = idx % G;
    int o = (idx / G) % C1;
    int b = idx / (G * C1);
    int t = g * 4;
    const float* xr = x + b * L0 + t;
    const float* wr = w + o * 32;
    float s0 = 0.f, s1 = 0.f, s2 = 0.f, s3 = 0.f;
    float x0 = xr[0], x1v = xr[1], x2v = xr[2];
#pragma unroll
    for (int k = 0; k < 32; k++) {
        float xn = xr[k + 3];
        float wv = __ldg(wr + k);
        s0 = fmaf(x0, wv, s0);
        s1 = fmaf(x1v, wv, s1);
        s2 = fmaf(x2v, wv, s2);
        s3 = fmaf(xn, wv, s3);
        x0 = x1v; x1v = x2v; x2v = xn;
    }
    float* out = &g_conv1[(b * C1 + o) * L1 + t];
    out[0] = s0; out[1] = s1; out[2] = s2; out[3] = s3;
}

__global__ void k_bnpart() {
    int c = blockIdx.x;
    int part = blockIdx.y;
    int tid = threadIdx.x;
    const int NP = B * L1 / 8;  // 11008
    int start = part * NP;
    double s = 0.0, s2 = 0.0;
    for (int i = start + tid; i < start + NP; i += 256) {
        int b = i / L1, t = i % L1;
        float v = g_conv1[(b * C1 + c) * L1 + t];
        s += (double)v;
        s2 += (double)v * (double)v;
    }
    __shared__ double sh[256], sh2[256];
    sh[tid] = s; sh2[tid] = s2;
    __syncthreads();
    for (int st = 128; st > 0; st >>= 1) {
        if (tid < st) { sh[tid] += sh[tid + st]; sh2[tid] += sh2[tid + st]; }
        __syncthreads();
    }
    if (tid == 0) {
        g_bns[(c * 8 + part) * 2 + 0] = sh[0];
        g_bns[(c * 8 + part) * 2 + 1] = sh2[0];
    }
}

__global__ void k_bnfin(const float* __restrict__ gg, const float* __restrict__ bb) {
    int c = threadIdx.x;
    if (c >= C1) return;
    double s = 0.0, s2 = 0.0;
    for (int p = 0; p < 8; p++) {
        s += g_bns[(c * 8 + p) * 2 + 0];
        s2 += g_bns[(c * 8 + p) * 2 + 1];
    }
    double n = (double)(B * L1);
    double mean = s / n;
    double var = s2 / n - mean * mean;
    float inv = rsqrtf((float)var + 1e-5f);
    float sc = gg[c] * inv;
    g_bn_scale[c] = sc;
    g_bn_shift[c] = bb[c] - (float)mean * sc;
}

__global__ void k_bnpool() {
    int idx = blockIdx.x * blockDim.x + threadIdx.x;
    if (idx >= B * C1 * L2) return;
    int l = idx % L2;
    int c = (idx / L2) % C1;
    int b = idx / (L2 * C1);
    const float* row = &g_conv1[(b * C1 + c) * L1 + 2 * l];
    float sc = g_bn_scale[c], sh = g_bn_shift[c];
    float m = -INFINITY;
#pragma unroll
    for (int i = 0; i < 3; i++) m = fmaxf(m, fmaxf(0.f, row[i] * sc + sh));
    g_xf[idx] = m;
}

__global__ void k_miu(const float* __restrict__ ap, const float* __restrict__ bp,
                      const float* __restrict__ an, const float* __restrict__ bn) {
    int idx = blockIdx.x * blockDim.x + threadIdx.x;
    if (idx >= B * C1 * L3) return;
    int l = idx % L3;
    int c = (idx / L3) % C1;
    int b = idx / (L3 * C1);
    const float* row = &g_xf[(b * C1 + c) * L2 + 2 * l];
    float a_p = ap[c], b_p = bp[c], a_n = an[c], b_n = bn[c];
    float mp = -INFINITY, mn = -INFINITY;
#pragma unroll
    for (int i = 0; i < 3; i++) {
        float v = row[i];
        mp = fmaxf(mp, sigfast(a_p * (v - b_p)));
        mn = fmaxf(mn, sigfast(-a_n * (v - b_n)));
    }
    g_xmiu[(b * CM + c) * L3 + l] = mp;
    g_xmiu[(b * CM + 16 + c) * L3 + l] = mn;
}

// ---------------- im2col / pool helpers ----------------

// channel-first source [b][IC][Lsrc] -> dst[(b*Lout+p)][IC*3] with symmetric pad
__global__ void k_im2col_cf(const float* __restrict__ src, float* __restrict__ dst,
                            int Lsrc, int Lout, int IC, int pad) {
    int idx = blockIdx.x * blockDim.x + threadIdx.x;
    int KW = IC * 3;
    if (idx >= B * Lout * KW) return;
    int k = idx % KW;
    int r = idx / KW;
    int p = r % Lout;
    int b = r / Lout;
    int ic = k / 3, kw = k % 3;
    int s = p - pad + kw;
    float v = 0.f;
    if (s >= 0 && s < Lsrc) v = src[(b * IC + ic) * Lsrc + s];
    dst[idx] = v;
}

// channel-last source [b][Lsrc][IC] -> dst[(b*Lout+p)][IC*3]
__global__ void k_im2col_cl(const float* __restrict__ src, float* __restrict__ dst,
                            int Lsrc, int Lout, int IC, int pad) {
    int idx = blockIdx.x * blockDim.x + threadIdx.x;
    int KW = IC * 3;
    if (idx >= B * Lout * KW) return;
    int k = idx % KW;
    int r = idx / KW;
    int p = r % Lout;
    int b = r / Lout;
    int ic = k / 3, kw = k % 3;
    int s = p - pad + kw;
    float v = 0.f;
    if (s >= 0 && s < Lsrc) v = src[(b * Lsrc + s) * IC + ic];
    dst[idx] = v;
}

// channel-last source [b][Lpre][IC], logically upsampled x2, pad 2
__global__ void k_im2col_up(const float* __restrict__ src, float* __restrict__ dst,
                            int Lpre, int Lout, int IC) {
    int idx = blockIdx.x * blockDim.x + threadIdx.x;
    int KW = IC * 3;
    if (idx >= B * Lout * KW) return;
    int k = idx % KW;
    int r = idx / KW;
    int p = r % Lout;
    int b = r / Lout;
    int ic = k / 3, kw = k % 3;
    int s = p - 2 + kw;
    float v = 0.f;
    if (s >= 0 && s < 2 * Lpre) v = up2cl(src + (b * Lpre) * IC + ic, IC, Lpre, s);
    dst[idx] = v;
}

// channel-last maxpool(3,2)
__global__ void k_pool_cl(const float* __restrict__ src, float* __restrict__ dst,
                          int Lin, int Lout, int C) {
    int idx = blockIdx.x * blockDim.x + threadIdx.x;
    if (idx >= B * Lout * C) return;
    int c = idx % C;
    int l = (idx / C) % Lout;
    int b = idx / (C * Lout);
    const float* s0 = &src[(b * Lin + 2 * l) * C + c];
    dst[idx] = fmaxf(fmaxf(s0[0], s0[C]), s0[2 * C]);
}

// ---------------- register-tiled GEMM ----------------
// C[M,N] = act(A[M,K] @ W[N,K]^T + bias[N]); BM=BN=64, BK=16, 4x4 per thread
// act: 0 none, 1 relu, 2 tanh, 3 sigmoid
__global__ void k_gemm64(const float* __restrict__ A, const float* __restrict__ W,
                         const float* __restrict__ bias, float* __restrict__ C,
                         int M, int N, int K, int act) {
    __shared__ float As[16][68];
    __shared__ float Bs[16][68];
    int tid = threadIdx.x;
    int tx = tid % 16, ty = tid / 16;
    int m0 = blockIdx.y * 64, n0 = blockIdx.x * 64;
    float acc[4][4] = {};
    for (int k0 = 0; k0 < K; k0 += 16) {
        int gk = k0 + tx;
        bool kv = (gk < K);
#pragma unroll
        for (int i = 0; i < 4; i++) {
            int r = ty + i * 16;
            int gm = m0 + r;
            As[tx][r] = (kv && gm < M) ? A[gm * K + gk] : 0.f;
            int gn = n0 + r;
            Bs[tx][r] = (kv && gn < N) ? W[gn * K + gk] : 0.f;
        }
        __syncthreads();
#pragma unroll
        for (int kk = 0; kk < 16; kk++) {
            float4 a = *reinterpret_cast<const float4*>(&As[kk][ty * 4]);
            float4 bq = *reinterpret_cast<const float4*>(&Bs[kk][tx * 4]);
            float av[4] = {a.x, a.y, a.z, a.w};
            float bv[4] = {bq.x, bq.y, bq.z, bq.w};
#pragma unroll
            for (int i = 0; i < 4; i++)
#pragma unroll
                for (int j = 0; j < 4; j++)
                    acc[i][j] = fmaf(av[i], bv[j], acc[i][j]);
        }
        __syncthreads();
    }
#pragma unroll
    for (int i = 0; i < 4; i++) {
        int gm = m0 + ty * 4 + i;
        if (gm >= M) continue;
#pragma unroll
        for (int j = 0; j < 4; j++) {
            int gn = n0 + tx * 4 + j;
            if (gn >= N) continue;
            float v = acc[i][j] + bias[gn];
            if (act == 1) v = fmaxf(v, 0.f);
            else if (act == 2) v = tanhf(v);
            else if (act == 3) v = sigfast(v);
            C[gm * N + gn] = v;
        }
    }
}

// ---------------- segmentation + logic ----------------

__global__ void k_seg() {
    int idx = blockIdx.x * blockDim.x + threadIdx.x;
    if (idx >= B * CM * LI) return;
    int l = idx % LI;
    int c = (idx / LI) % CM;
    int b = idx / (LI * CM);
    const float* h4r = &g_h4[(b * L9 + l) * 32 + c];
    float wv = fmaxf(fmaxf(h4r[0], h4r[32]), fmaxf(h4r[64], h4r[96]));
    float xm = g_xmiu[(b * CM + c) * L3 + l];
    float prod = wv * xm;
#pragma unroll
    for (int k = 0; k < 5; k++) {
        float lo = (float)k * 0.2f;
        float hi = (k == 4) ? 2.0f : (float)(k + 1) * 0.2f;
        bool on = (wv >= lo) && (wv < hi);
        g_inp[(b * CI + k * 32 + c) * LI + l] = on ? prod : 0.f;
    }
}

// logs + until (== max(0, min(x[t], x[t+1])))
__global__ void k_until_logs() {
    int idx = blockIdx.x * blockDim.x + threadIdx.x;
    if (idx >= B * CI * LI) return;
    int l = idx % LI;
    int c = (idx / LI) % CI;
    int b = idx / (LI * CI);
    float v = g_inp[idx];
    float cv = fminf(fmaxf(v, 0.f), 1.f);
    g_logp[idx] = __logf(cv + EPSL);
    g_logq[idx] = __logf(1.0f - cv + EPSL);
    if (l < LU) {
        float v2 = g_inp[idx + 1];
        g_x1[(b * C_X1 + 40 + c) * LU + l] = fmaxf(0.f, fminf(v, v2));
    }
}

__global__ void k_softmax_w(const float* __restrict__ w, float* __restrict__ out, int sz) {
    int o = blockIdx.x;
    int tid = threadIdx.x;
    const float* row = w + o * sz;
    __shared__ float red[64];
    float mx = -INFINITY;
    for (int i = tid; i < sz; i += 64) mx = fmaxf(mx, row[i]);
    red[tid] = mx; __syncthreads();
    for (int s = 32; s > 0; s >>= 1) { if (tid < s) red[tid] = fmaxf(red[tid], red[tid + s]); __syncthreads(); }
    mx = red[0]; __syncthreads();
    float sm = 0.f;
    for (int i = tid; i < sz; i += 64) sm += expf(row[i] - mx);
    red[tid] = sm; __syncthreads();
    for (int s = 32; s > 0; s >>= 1) { if (tid < s) red[tid] += red[tid + s]; __syncthreads(); }
    sm = red[0];
    for (int i = tid; i < sz; i += 64) out[o * sz + i] = expf(row[i] - mx) / sm;
}

// logic layer 1: thread owns (b,t), 20 accumulators. blockIdx.y: 0=and, 1=or.
__global__ void k_logic1() {
    __shared__ float sw[20 * CI * 2];  // 25.6KB
    int tid = threadIdx.x;
    int type = blockIdx.y;
    const float* wsrc = type == 0 ? g_wn_and2 : g_wn_or2;
    for (int i = tid; i < 20 * CI * 2; i += 128) sw[i] = wsrc[i];
    __syncthreads();
    int idx = blockIdx.x * 128 + tid;
    if (idx >= B * LU) return;
    int t = idx % LU, b = idx / LU;
    float acc[20] = {};
    const float* lp = (type == 0 ? g_logp : g_logq) + b * CI * LI + t;
    for (int c = 0; c < CI; c++) {
        float p0 = lp[c * LI], p1 = lp[c * LI + 1];
#pragma unroll
        for (int o = 0; o < 20; o++) {
            acc[o] = fmaf(sw[o * 320 + 2 * c], p0, acc[o]);
            acc[o] = fmaf(sw[o * 320 + 2 * c + 1], p1, acc[o]);
        }
    }
    float* x1 = &g_x1[(b * C_X1 + (type == 0 ? 0 : 20)) * LU + t];
    if (type == 0) {
#pragma unroll
        for (int o = 0; o < 20; o++) x1[o * LU] = fmaxf(0.f, __expf(acc[o]));
    } else {
#pragma unroll
        for (int o = 0; o < 20; o++) x1[o * LU] = fmaxf(0.f, 1.0f - __expf(acc[o]));
    }
}

__global__ void k_logs1() {
    int idx = blockIdx.x * blockDim.x + threadIdx.x;
    if (idx >= B * C_X1 * LU) return;
    float v = g_x1[idx];
    float cv = fminf(fmaxf(v, 0.f), 1.f);
    g_logp1[idx] = __logf(cv + EPSL);
    g_logq1[idx] = __logf(1.0f - cv + EPSL);
}

// logic layer 2: thread owns (b,t), 6 and + 6 or accumulators
__global__ void k_logic2() {
    __shared__ float swa[6 * C_X1 * 2];  // 9.6KB
    __shared__ float swo[6 * C_X1 * 2];
    int tid = threadIdx.x;
    for (int i = tid; i < 6 * C_X1 * 2; i += 128) { swa[i] = g_wn_and[i]; swo[i] = g_wn_or[i]; }
    __syncthreads();
    int idx = blockIdx.x * 128 + tid;
    if (idx >= B * LU) return;
    int t = idx % LU, b = idx / LU;
    float sa[6] = {}, so[6] = {};
    bool hasL = (t > 0);
    const float* lp = &g_logp1[b * C_X1 * LU + t];
    const float* lq = &g_logq1[b * C_X1 * LU + t];
    for (int c = 0; c < C_X1; c++) {
        float p1 = lp[c * LU];
        float q1 = lq[c * LU];
        float p0 = hasL ? lp[c * LU - 1] : 0.f;
        float q0 = hasL ? lq[c * LU - 1] : 0.f;
#pragma unroll
        for (int o = 0; o < 6; o++) {
            sa[o] = fmaf(swa[o * 400 + 2 * c], p0, sa[o]);
            sa[o] = fmaf(swa[o * 400 + 2 * c + 1], p1, sa[o]);
            so[o] = fmaf(swo[o * 400 + 2 * c], q0, so[o]);
            so[o] = fmaf(swo[o * 400 + 2 * c + 1], q1, so[o]);
        }
    }
#pragma unroll
    for (int o = 0; o < 6; o++) {
        g_x2[(b * 12 + o) * LU + t] = fmaxf(0.f, __expf(sa[o]));
        g_x2[(b * 12 + 6 + o) * LU + t] = fmaxf(0.f, 1.0f - __expf(so[o]));
    }
}

// final tiny FC: N=10
__global__ void k_fc3(const float* __restrict__ A, const float* __restrict__ W,
                      const float* __restrict__ bias, float* __restrict__ C) {
    int idx = blockIdx.x * blockDim.x + threadIdx.x;
    if (idx >= B * 12 * 10) return;
    int m = idx / 10, n = idx % 10;
    float s = bias[n];
    const float* a = A + m * 256;
    const float* w = W + n * 256;
#pragma unroll 8
    for (int k = 0; k < 256; k++) s = fmaf(a[k], __ldg(w + k), s);
    C[idx] = s;
}

// ---------------- launcher ----------------

extern "C" void kernel_launch(void* const* d_in, const int* in_sizes, int n_in,
                              void* d_out, int out_size) {
    const float* x      = (const float*)d_in[0];
    const float* wave_w = (const float*)d_in[1];
    const float* bn_g   = (const float*)d_in[2];
    const float* bn_b   = (const float*)d_in[3];
    const float* miu_ap = (const float*)d_in[4];
    const float* miu_bp = (const float*)d_in[5];
    const float* miu_an = (const float*)d_in[6];
    const float* miu_bn = (const float*)d_in[7];
    const float* ae_w1  = (const float*)d_in[8];
    const float* ae_b1  = (const float*)d_in[9];
    const float* ae_w2  = (const float*)d_in[10];
    const float* ae_b2  = (const float*)d_in[11];
    const float* ae_w3  = (const float*)d_in[12];
    const float* ae_b3  = (const float*)d_in[13];
    const float* ae_w4  = (const float*)d_in[14];
    const float* ae_b4  = (const float*)d_in[15];
    const float* and2_w = (const float*)d_in[16];
    const float* or2_w  = (const float*)d_in[17];
    const float* and_w  = (const float*)d_in[18];
    const float* or_w   = (const float*)d_in[19];
    const float* fc1_w  = (const float*)d_in[20];
    const float* fc1_b  = (const float*)d_in[21];
    const float* fc2_w  = (const float*)d_in[22];
    const float* fc2_b  = (const float*)d_in[23];
    const float* fc3_w  = (const float*)d_in[24];
    const float* fc3_b  = (const float*)d_in[25];
    float* out = (float*)d_out;

    const int T = 256;

    // front-end
    k_conv1<<<cdiv(B * C1 * (L1 / 4), T), T>>>(x, wave_w);
    k_bnpart<<<dim3(C1, 8), 256>>>();
    k_bnfin<<<1, 32>>>(bn_g, bn_b);
    k_bnpool<<<cdiv(B * C1 * L2, T), T>>>();
    k_miu<<<cdiv(B * C1 * L3, T), T>>>(miu_ap, miu_bp, miu_an, miu_bn);

    float *pA1, *pT1, *ph1, *pA2, *pT2, *ph2, *pA3, *ph3, *pA4, *ph4;
    cudaGetSymbolAddress((void**)&pA1, g_A1);
    cudaGetSymbolAddress((void**)&pT1, g_T1);
    cudaGetSymbolAddress((void**)&ph1, g_h1);
    cudaGetSymbolAddress((void**)&pA2, g_A2);
    cudaGetSymbolAddress((void**)&pT2, g_T2);
    cudaGetSymbolAddress((void**)&ph2, g_h2);
    cudaGetSymbolAddress((void**)&pA3, g_A3);
    cudaGetSymbolAddress((void**)&ph3, g_h3);
    cudaGetSymbolAddress((void**)&pA4, g_A4);
    cudaGetSymbolAddress((void**)&ph4, g_h4);
    float* pxmiu; cudaGetSymbolAddress((void**)&pxmiu, g_xmiu);

    // ae1: conv(pad1)+tanh over x_miu -> pool
    k_im2col_cf<<<cdiv(B * L3 * 96, T), T>>>(pxmiu, pA1, L3, L3, 32, 1);
    k_gemm64<<<dim3(1, (B * L3 + 63) / 64), 256>>>(pA1, ae_w1, ae_b1, pT1, B * L3, 64, 96, 2);
    k_pool_cl<<<cdiv(B * L4 * 64, T), T>>>(pT1, ph1, L3, L4, 64);
    // ae2
    k_im2col_cl<<<cdiv(B * L4 * 192, T), T>>>(ph1, pA2, L4, L4, 64, 1);
    k_gemm64<<<dim3(1, (B * L4 + 63) / 64), 256>>>(pA2, ae_w2, ae_b2, pT2, B * L4, 32, 192, 1);
    k_pool_cl<<<cdiv(B * L5 * 32, T), T>>>(pT2, ph2, L4, L5, 32);
    // ae3: upsample + conv(pad2) + tanh
    k_im2col_up<<<cdiv(B * L7 * 96, T), T>>>(ph2, pA3, L5, L7, 32);
    k_gemm64<<<dim3(1, (B * L7 + 63) / 64), 256>>>(pA3, ae_w3, ae_b3, ph3, B * L7, 64, 96, 2);
    // ae4: upsample + conv(pad2) + sigmoid
    k_im2col_up<<<cdiv(B * L9 * 192, T), T>>>(ph3, pA4, L7, L9, 64);
    k_gemm64<<<dim3(1, (B * L9 + 63) / 64), 256>>>(pA4, ae_w4, ae_b4, ph4, B * L9, 32, 192, 3);

    // segmentation + until + logs
    k_seg<<<cdiv(B * CM * LI, T), T>>>();
    k_until_logs<<<cdiv(B * CI * LI, T), T>>>();

    {
        float* p;
        cudaGetSymbolAddress((void**)&p, g_wn_and2);
        k_softmax_w<<<20, 64>>>(and2_w, p, CI * 2);
        cudaGetSymbolAddress((void**)&p, g_wn_or2);
        k_softmax_w<<<20, 64>>>(or2_w, p, CI * 2);
        cudaGetSymbolAddress((void**)&p, g_wn_and);
        k_softmax_w<<<6, 64>>>(and_w, p, C_X1 * 2);
        cudaGetSymbolAddress((void**)&p, g_wn_or);
        k_softmax_w<<<6, 64>>>(or_w, p, C_X1 * 2);
    }

    k_logic1<<<dim3(cdiv(B * LU, 128), 2), 128>>>();
    k_logs1<<<cdiv(B * C_X1 * LU, T), T>>>();
    k_logic2<<<cdiv(B * LU, 128), 128>>>();

    float *px2, *pf1, *pf2;
    cudaGetSymbolAddress((void**)&px2, g_x2);
    cudaGetSymbolAddress((void**)&pf1, g_fc1o);
    cudaGetSymbolAddress((void**)&pf2, g_fc2o);

    k_gemm64<<<dim3(1024 / 64, (B * 12) / 64), 256>>>(px2, fc1_w, fc1_b, pf1, B * 12, 1024, LU, 1);
    k_gemm64<<<dim3(256 / 64, (B * 12) / 64), 256>>>(pf1, fc2_w, fc2_b, pf2, B * 12, 256, 1024, 1);
    k_fc3<<<cdiv(B * 12 * 10, T), T>>>(pf2, fc3_w, fc3_b, out);

    (void)in_sizes; (void)n_in; (void)out_size;
}

// round 3
// speedup vs baseline: 2.2657x; 1.1704x over previous
#include <cuda_runtime.h>
#include <math.h>

#define B    128
#define C1   16
#define L0   719
#define L1   688
#define L2   343
#define L3   171
#define CM   32
#define L4   85
#define L5   42
#define L7   86
#define L9   174
#define CI   160
#define LI   171
#define LU   170
#define C_X1 200
#define EPSL 1e-6f

// ---------------- scratch ----------------
__device__ float  g_conv1[B*C1*L1];
__device__ double g_bns[C1*B*2];
__device__ float  g_bn_scale[C1];
__device__ float  g_bn_shift[C1];
__device__ float  g_xmiu[B*CM*L3];     // channel-first
__device__ float  g_T1[B*L3*64];       // channel-last
__device__ float  g_T2[B*L4*32];       // channel-last
__device__ float  g_h3[B*L7*64];       // channel-last
__device__ float  g_h4[B*32*L9];       // channel-FIRST
__device__ float  g_inp[B*CI*LI];      // channel-first
__device__ float  g_x1[B*C_X1*LU];     // channel-first
__device__ float  g_x2[B*12*LU];
__device__ float  g_fc1o[B*12*1024];
__device__ float  g_fc2o[B*12*256];
__device__ float  g_wn_and2[20*CI*2];
__device__ float  g_wn_or2 [20*CI*2];
__device__ float  g_wn_and [6*C_X1*2];
__device__ float  g_wn_or  [6*C_X1*2];

static inline int cdiv(int a, int b) { return (a + b - 1) / b; }

__device__ __forceinline__ float sigfast(float z) {
    return __fdividef(1.0f, 1.0f + __expf(-z));
}

// ---------------- conv1 + BN partial stats ----------------
// block = (c = blockIdx.x, b = blockIdx.y), 256 threads (172 active, 4 outputs each)
__global__ void k_conv1(const float* __restrict__ x, const float* __restrict__ w) {
    int c = blockIdx.x, b = blockIdx.y;
    int tid = threadIdx.x;
    double ls = 0.0, ls2 = 0.0;
    if (tid < L1 / 4) {
        int t = tid * 4;
        const float* xr = x + b * L0 + t;
        const float* wr = w + c * 32;
        float s0 = 0.f, s1 = 0.f, s2 = 0.f, s3 = 0.f;
        float x0 = xr[0], x1v = xr[1], x2v = xr[2];
#pragma unroll
        for (int k = 0; k < 32; k++) {
            float xn = xr[k + 3];
            float wv = __ldg(wr + k);
            s0 = fmaf(x0, wv, s0);
            s1 = fmaf(x1v, wv, s1);
            s2 = fmaf(x2v, wv, s2);
            s3 = fmaf(xn, wv, s3);
            x0 = x1v; x1v = x2v; x2v = xn;
        }
        float* out = &g_conv1[(b * C1 + c) * L1 + t];
        out[0] = s0; out[1] = s1; out[2] = s2; out[3] = s3;
        ls = (double)s0 + (double)s1 + (double)s2 + (double)s3;
        ls2 = (double)s0*s0 + (double)s1*s1 + (double)s2*s2 + (double)s3*s3;
    }
    __shared__ double sh[256], sh2[256];
    sh[tid] = ls; sh2[tid] = ls2;
    __syncthreads();
    for (int st = 128; st > 0; st >>= 1) {
        if (tid < st) { sh[tid] += sh[tid + st]; sh2[tid] += sh2[tid + st]; }
        __syncthreads();
    }
    if (tid == 0) {
        g_bns[(c * B + b) * 2 + 0] = sh[0];
        g_bns[(c * B + b) * 2 + 1] = sh2[0];
    }
}

// 1 block, 512 threads: warp per channel
__global__ void k_bnfin(const float* __restrict__ gg, const float* __restrict__ bb) {
    int tid = threadIdx.x;
    int c = tid >> 5, lane = tid & 31;
    double s = 0.0, s2 = 0.0;
    for (int p = lane; p < B; p += 32) {
        s  += g_bns[(c * B + p) * 2 + 0];
        s2 += g_bns[(c * B + p) * 2 + 1];
    }
#pragma unroll
    for (int off = 16; off > 0; off >>= 1) {
        s  += __shfl_down_sync(0xffffffff, s, off);
        s2 += __shfl_down_sync(0xffffffff, s2, off);
    }
    if (lane == 0) {
        double n = (double)(B * L1);
        double mean = s / n;
        double var = s2 / n - mean * mean;
        float inv = rsqrtf((float)var + 1e-5f);
        float sc = gg[c] * inv;
        g_bn_scale[c] = sc;
        g_bn_shift[c] = bb[c] - (float)mean * sc;
    }
}

// fused bn + relu + pool(3,2) + miu + pool(3,2) : conv1 -> x_miu
__global__ void k_front(const float* __restrict__ ap, const float* __restrict__ bp,
                        const float* __restrict__ an, const float* __restrict__ bn) {
    int idx = blockIdx.x * blockDim.x + threadIdx.x;
    if (idx >= B * C1 * L3) return;
    int l = idx % L3;
    int c = (idx / L3) % C1;
    int b = idx / (L3 * C1);
    const float* cr = &g_conv1[(b * C1 + c) * L1 + 4 * l];
    float sc = g_bn_scale[c], sh = g_bn_shift[c];
    float a[7];
#pragma unroll
    for (int i = 0; i < 7; i++) a[i] = fmaxf(0.f, fmaf(cr[i], sc, sh));
    float xf0 = fmaxf(fmaxf(a[0], a[1]), a[2]);
    float xf1 = fmaxf(fmaxf(a[2], a[3]), a[4]);
    float xf2 = fmaxf(fmaxf(a[4], a[5]), a[6]);
    float a_p = ap[c], b_p = bp[c], a_n = an[c], b_n = bn[c];
    float mp = fmaxf(fmaxf(sigfast(a_p * (xf0 - b_p)), sigfast(a_p * (xf1 - b_p))),
                     sigfast(a_p * (xf2 - b_p)));
    float mn = fmaxf(fmaxf(sigfast(-a_n * (xf0 - b_n)), sigfast(-a_n * (xf1 - b_n))),
                     sigfast(-a_n * (xf2 - b_n)));
    g_xmiu[(b * CM + c) * L3 + l] = mp;
    g_xmiu[(b * CM + 16 + c) * L3 + l] = mn;
}

// ---------------- fused conv-GEMM (staging + register tiles) ----------------
// MODE0: xmiu(cf,32ch,L171) pad1 -> tanh -> T1(cl,64ch,L171)          MT=64
// MODE1: pool3,2(T1)(->85) pad1 -> relu -> T2(cl,32ch,L85)            MT=64
// MODE2: pool3,2(T2)(->42) up2(->84) pad2 -> tanh -> h3(cl,64ch,L86)  MT=64
// MODE3: up2(h3)(->172) pad2 -> sigmoid -> h4(CHANNEL-FIRST,32ch,L174) MT=32
template<int MODE>
__global__ void k_ae(const float* __restrict__ in, const float* __restrict__ w,
                     const float* __restrict__ bias, float* __restrict__ out) {
    constexpr int IC   = (MODE == 0 || MODE == 2) ? 32 : 64;
    constexpr int OC   = (MODE == 0 || MODE == 2) ? 64 : 32;
    constexpr int PAD  = (MODE < 2) ? 1 : 2;
    constexpr int MT   = (MODE == 3) ? 32 : 64;
    constexpr int NTH  = (MODE == 3) ? 128 : 256;
    constexpr int LOUT = (MODE == 0) ? 171 : (MODE == 1) ? 85 : (MODE == 2) ? 86 : 174;
    constexpr int ROWS = MT + 2 * PAD;
    constexpr int ICP  = IC + 1;
    constexpr int NT   = OC / 4;
    constexpr int TYC  = NTH / NT;
    constexpr int TM   = MT / TYC;

    __shared__ float sW[3 * IC * OC];
    __shared__ float sIn[ROWS * ICP];
    __shared__ float sH[(MODE == 2) ? (42 * 33) : (MODE == 3) ? (22 * 65) : 1];

    int tid = threadIdx.x;
    int b = blockIdx.y;
    int p0 = blockIdx.x * MT;

    // weights: sW[(kw*IC+ic)*OC + oc]
    for (int i = tid; i < OC * IC * 3; i += NTH) {
        int k = i % (IC * 3), oc = i / (IC * 3);
        int ic = k / 3, kw = k % 3;
        sW[(kw * IC + ic) * OC + oc] = w[oc * IC * 3 + k];
    }

    if (MODE == 0) {
        for (int i = tid; i < ROWS * IC; i += NTH) {
            int ic = i / ROWS, row = i % ROWS;
            int s = p0 - 1 + row;
            sIn[row * ICP + ic] = (s >= 0 && s < L3) ? in[(b * IC + ic) * L3 + s] : 0.f;
        }
    } else if (MODE == 1) {
        for (int i = tid; i < ROWS * IC; i += NTH) {
            int ic = i % IC, row = i / IC;
            int s = p0 - 1 + row;
            float v = 0.f;
            if (s >= 0 && s < L4) {
                const float* t1 = &in[(b * L3 + 2 * s) * 64 + ic];
                v = fmaxf(fmaxf(t1[0], t1[64]), t1[128]);
            }
            sIn[row * ICP + ic] = v;
        }
    } else if (MODE == 2) {
        for (int i = tid; i < 42 * 32; i += NTH) {
            int ic = i % 32, j = i / 32;
            const float* t2 = &in[(b * L4 + 2 * j) * 32 + ic];
            sH[j * 33 + ic] = fmaxf(fmaxf(t2[0], t2[32]), t2[64]);
        }
        __syncthreads();
        for (int i = tid; i < ROWS * IC; i += NTH) {
            int ic = i % 32, row = i / 32;
            int u = p0 - 2 + row;
            float v = 0.f;
            if (u >= 0 && u < 84) {
                int j = u >> 1, a, b2; float wa, wb;
                if (u & 1) { a = j; b2 = min(j + 1, 41); wa = 0.75f; wb = 0.25f; }
                else       { a = max(j - 1, 0); b2 = j;  wa = 0.25f; wb = 0.75f; }
                v = wa * sH[a * 33 + ic] + wb * sH[b2 * 33 + ic];
            }
            sIn[row * ICP + ic] = v;
        }
    } else {  // MODE 3
        int jb = max(0, (p0 - 2) / 2 - 1);
        int je = min(L7 - 1, (p0 + MT + 1) / 2 + 1);
        int nj = je - jb + 1;
        for (int i = tid; i < nj * 64; i += NTH) {
            int ic = i % 64, jj = i / 64;
            sH[jj * 65 + ic] = in[(b * L7 + jb + jj) * 64 + ic];
        }
        __syncthreads();
        for (int i = tid; i < ROWS * IC; i += NTH) {
            int ic = i % 64, row = i / 64;
            int u = p0 - 2 + row;
            float v = 0.f;
            if (u >= 0 && u < 2 * L7) {
                int j = u >> 1, a, b2; float wa, wb;
                if (u & 1) { a = j; b2 = min(j + 1, L7 - 1); wa = 0.75f; wb = 0.25f; }
                else       { a = max(j - 1, 0); b2 = j;      wa = 0.25f; wb = 0.75f; }
                v = wa * sH[(a - jb) * 65 + ic] + wb * sH[(b2 - jb) * 65 + ic];
            }
            sIn[row * ICP + ic] = v;
        }
    }
    __syncthreads();

    int tx = tid % NT, ty = tid / NT;
    float acc[TM][4] = {};
#pragma unroll
    for (int kw = 0; kw < 3; kw++) {
#pragma unroll 4
        for (int ic = 0; ic < IC; ic++) {
            float4 wv = *reinterpret_cast<const float4*>(&sW[(kw * IC + ic) * OC + tx * 4]);
#pragma unroll
            for (int i = 0; i < TM; i++) {
                float a = sIn[(ty * TM + i + kw) * ICP + ic];
                acc[i][0] = fmaf(a, wv.x, acc[i][0]);
                acc[i][1] = fmaf(a, wv.y, acc[i][1]);
                acc[i][2] = fmaf(a, wv.z, acc[i][2]);
                acc[i][3] = fmaf(a, wv.w, acc[i][3]);
            }
        }
    }

#pragma unroll
    for (int i = 0; i < TM; i++) {
        int gm = p0 + ty * TM + i;
        if (gm >= LOUT) continue;
        float v[4];
#pragma unroll
        for (int j = 0; j < 4; j++) {
            float t = acc[i][j] + __ldg(bias + tx * 4 + j);
            if (MODE == 1) t = fmaxf(t, 0.f);
            else if (MODE == 3) t = sigfast(t);
            else t = tanhf(t);
            v[j] = t;
        }
        if (MODE == 3) {
#pragma unroll
            for (int j = 0; j < 4; j++)
                out[(b * 32 + tx * 4 + j) * L9 + gm] = v[j];
        } else {
            *reinterpret_cast<float4*>(&out[(b * LOUT + gm) * OC + tx * 4]) =
                make_float4(v[0], v[1], v[2], v[3]);
        }
    }
}

// ---------------- seg + until fused ----------------
__device__ __forceinline__ int binof(float wv) {
    return (wv >= 0.8f) ? 4 : (wv >= 0.6f) ? 3 : (wv >= 0.4f) ? 2 : (wv >= 0.2f) ? 1 : 0;
}

__global__ void k_seg() {
    int idx = blockIdx.x * blockDim.x + threadIdx.x;
    if (idx >= B * CM * LI) return;
    int l = idx % LI;
    int c = (idx / LI) % CM;
    int b = idx / (LI * CM);
    const float* h4r = &g_h4[(b * 32 + c) * L9 + l];
    float wv = fmaxf(fmaxf(h4r[0], h4r[1]), fmaxf(h4r[2], h4r[3]));
    float xm = g_xmiu[(b * CM + c) * L3 + l];
    float prod = wv * xm;
    int kl = binof(wv);
#pragma unroll
    for (int k = 0; k < 5; k++)
        g_inp[((b * 5 + k) * 32 + c) * LI + l] = (k == kl) ? prod : 0.f;
    if (l < LU) {
        float wv2 = fmaxf(fmaxf(h4r[1], h4r[2]), fmaxf(h4r[3], h4r[4]));
        float prod2 = wv2 * g_xmiu[(b * CM + c) * L3 + l + 1];
        int k2 = binof(wv2);
        float u = fmaxf(0.f, fminf(prod, prod2));
#pragma unroll
        for (int k = 0; k < 5; k++)
            g_x1[(b * C_X1 + 40 + k * 32 + c) * LU + l] =
                (k == kl && k == k2) ? u : 0.f;
    }
}

// ---------------- softmax (all 4 weight tensors, one launch) ----------------
__global__ void k_softmax_all(const float* __restrict__ and2_w, const float* __restrict__ or2_w,
                              const float* __restrict__ and_w, const float* __restrict__ or_w) {
    int blk = blockIdx.x;
    const float* src; float* dst; int sz, o;
    if (blk < 20)      { src = and2_w; dst = g_wn_and2; sz = 320; o = blk; }
    else if (blk < 40) { src = or2_w;  dst = g_wn_or2;  sz = 320; o = blk - 20; }
    else if (blk < 46) { src = and_w;  dst = g_wn_and;  sz = 400; o = blk - 40; }
    else               { src = or_w;   dst = g_wn_or;   sz = 400; o = blk - 46; }
    const float* row = src + o * sz;
    int tid = threadIdx.x;
    __shared__ float red[64];
    float mx = -INFINITY;
    for (int i = tid; i < sz; i += 64) mx = fmaxf(mx, row[i]);
    red[tid] = mx; __syncthreads();
    for (int s = 32; s > 0; s >>= 1) { if (tid < s) red[tid] = fmaxf(red[tid], red[tid + s]); __syncthreads(); }
    mx = red[0]; __syncthreads();
    float sm = 0.f;
    for (int i = tid; i < sz; i += 64) sm += expf(row[i] - mx);
    red[tid] = sm; __syncthreads();
    for (int s = 32; s > 0; s >>= 1) { if (tid < s) red[tid] += red[tid + s]; __syncthreads(); }
    sm = red[0];
    for (int i = tid; i < sz; i += 64) dst[o * sz + i] = expf(row[i] - mx) / sm;
}

// ---------------- logic layer 1 (logs inline) ----------------
__global__ void k_logic1() {
    __shared__ float2 sw2[20 * CI];  // 25.6KB
    int tid = threadIdx.x;
    int type = blockIdx.y;
    const float2* wsrc = reinterpret_cast<const float2*>(type == 0 ? g_wn_and2 : g_wn_or2);
    for (int i = tid; i < 20 * CI; i += 128) sw2[i] = wsrc[i];
    __syncthreads();
    int idx = blockIdx.x * 128 + tid;
    if (idx >= B * LU) return;
    int t = idx % LU, b = idx / LU;
    float acc[20] = {};
    const float* ip = g_inp + b * CI * LI + t;
    for (int c = 0; c < CI; c++) {
        float v0 = ip[c * LI], v1 = ip[c * LI + 1];
        float cv0 = fminf(fmaxf(v0, 0.f), 1.f);
        float cv1 = fminf(fmaxf(v1, 0.f), 1.f);
        float p0, p1;
        if (type == 0) { p0 = __logf(cv0 + EPSL);        p1 = __logf(cv1 + EPSL); }
        else           { p0 = __logf(1.0f - cv0 + EPSL); p1 = __logf(1.0f - cv1 + EPSL); }
#pragma unroll
        for (int o = 0; o < 20; o++) {
            float2 w2 = sw2[o * CI + c];
            acc[o] = fmaf(w2.x, p0, acc[o]);
            acc[o] = fmaf(w2.y, p1, acc[o]);
        }
    }
    float* x1 = &g_x1[(b * C_X1 + (type == 0 ? 0 : 20)) * LU + t];
    if (type == 0) {
#pragma unroll
        for (int o = 0; o < 20; o++) x1[o * LU] = fmaxf(0.f, __expf(acc[o]));
    } else {
#pragma unroll
        for (int o = 0; o < 20; o++) x1[o * LU] = fmaxf(0.f, 1.0f - __expf(acc[o]));
    }
}

// ---------------- logic layer 2 (logs inline) ----------------
__global__ void k_logic2() {
    __shared__ float2 swa2[6 * C_X1];
    __shared__ float2 swo2[6 * C_X1];
    int tid = threadIdx.x;
    const float2* wa = reinterpret_cast<const float2*>(g_wn_and);
    const float2* wo = reinterpret_cast<const float2*>(g_wn_or);
    for (int i = tid; i < 6 * C_X1; i += 128) { swa2[i] = wa[i]; swo2[i] = wo[i]; }
    __syncthreads();
    int idx = blockIdx.x * 128 + tid;
    if (idx >= B * LU) return;
    int t = idx % LU, b = idx / LU;
    float sa[6] = {}, so[6] = {};
    bool hasL = (t > 0);
    const float* xp = &g_x1[b * C_X1 * LU + t];
    for (int c = 0; c < C_X1; c++) {
        float v1 = xp[c * LU];
        float cv1 = fminf(fmaxf(v1, 0.f), 1.f);
        float p1 = __logf(cv1 + EPSL);
        float q1 = __logf(1.0f - cv1 + EPSL);
        float p0 = 0.f, q0 = 0.f;
        if (hasL) {
            float v0 = xp[c * LU - 1];
            float cv0 = fminf(fmaxf(v0, 0.f), 1.f);
            p0 = __logf(cv0 + EPSL);
            q0 = __logf(1.0f - cv0 + EPSL);
        }
#pragma unroll
        for (int o = 0; o < 6; o++) {
            float2 a2 = swa2[o * C_X1 + c];
            float2 o2 = swo2[o * C_X1 + c];
            sa[o] = fmaf(a2.x, p0, sa[o]);
            sa[o] = fmaf(a2.y, p1, sa[o]);
            so[o] = fmaf(o2.x, q0, so[o]);
            so[o] = fmaf(o2.y, q1, so[o]);
        }
    }
#pragma unroll
    for (int o = 0; o < 6; o++) {
        g_x2[(b * 12 + o) * LU + t] = fmaxf(0.f, __expf(sa[o]));
        g_x2[(b * 12 + 6 + o) * LU + t] = fmaxf(0.f, 1.0f - __expf(so[o]));
    }
}

// ---------------- FC GEMM (64x64x16, 4x4 microtile) ----------------
__global__ void k_gemm64(const float* __restrict__ A, const float* __restrict__ W,
                         const float* __restrict__ bias, float* __restrict__ C,
                         int M, int N, int K, int relu) {
    __shared__ float As[16][68];
    __shared__ float Bs[16][68];
    int tid = threadIdx.x;
    int tx = tid % 16, ty = tid / 16;
    int m0 = blockIdx.y * 64, n0 = blockIdx.x * 64;
    float acc[4][4] = {};
    for (int k0 = 0; k0 < K; k0 += 16) {
        int gk = k0 + tx;
        bool kv = (gk < K);
#pragma unroll
        for (int i = 0; i < 4; i++) {
            int r = ty + i * 16;
            int gm = m0 + r;
            As[tx][r] = (kv && gm < M) ? A[gm * K + gk] : 0.f;
            int gn = n0 + r;
            Bs[tx][r] = (kv && gn < N) ? W[gn * K + gk] : 0.f;
        }
        __syncthreads();
#pragma unroll
        for (int kk = 0; kk < 16; kk++) {
            float4 a = *reinterpret_cast<const float4*>(&As[kk][ty * 4]);
            float4 bq = *reinterpret_cast<const float4*>(&Bs[kk][tx * 4]);
            float av[4] = {a.x, a.y, a.z, a.w};
            float bv[4] = {bq.x, bq.y, bq.z, bq.w};
#pragma unroll
            for (int i = 0; i < 4; i++)
#pragma unroll
                for (int j = 0; j < 4; j++)
                    acc[i][j] = fmaf(av[i], bv[j], acc[i][j]);
        }
        __syncthreads();
    }
#pragma unroll
    for (int i = 0; i < 4; i++) {
        int gm = m0 + ty * 4 + i;
        if (gm >= M) continue;
#pragma unroll
        for (int j = 0; j < 4; j++) {
            int gn = n0 + tx * 4 + j;
            if (gn >= N) continue;
            float v = acc[i][j] + bias[gn];
            if (relu) v = fmaxf(v, 0.f);
            C[gm * N + gn] = v;
        }
    }
}

__global__ void k_fc3(const float* __restrict__ A, const float* __restrict__ W,
                      const float* __restrict__ bias, float* __restrict__ C) {
    int idx = blockIdx.x * blockDim.x + threadIdx.x;
    if (idx >= B * 12 * 10) return;
    int m = idx / 10, n = idx % 10;
    float s = bias[n];
    const float* a = A + m * 256;
    const float* w = W + n * 256;
#pragma unroll 8
    for (int k = 0; k < 256; k++) s = fmaf(a[k], __ldg(w + k), s);
    C[idx] = s;
}

// ---------------- launcher ----------------

extern "C" void kernel_launch(void* const* d_in, const int* in_sizes, int n_in,
                              void* d_out, int out_size) {
    const float* x      = (const float*)d_in[0];
    const float* wave_w = (const float*)d_in[1];
    const float* bn_g   = (const float*)d_in[2];
    const float* bn_b   = (const float*)d_in[3];
    const float* miu_ap = (const float*)d_in[4];
    const float* miu_bp = (const float*)d_in[5];
    const float* miu_an = (const float*)d_in[6];
    const float* miu_bn = (const float*)d_in[7];
    const float* ae_w1  = (const float*)d_in[8];
    const float* ae_b1  = (const float*)d_in[9];
    const float* ae_w2  = (const float*)d_in[10];
    const float* ae_b2  = (const float*)d_in[11];
    const float* ae_w3  = (const float*)d_in[12];
    const float* ae_b3  = (const float*)d_in[13];
    const float* ae_w4  = (const float*)d_in[14];
    const float* ae_b4  = (const float*)d_in[15];
    const float* and2_w = (const float*)d_in[16];
    const float* or2_w  = (const float*)d_in[17];
    const float* and_w  = (const float*)d_in[18];
    const float* or_w   = (const float*)d_in[19];
    const float* fc1_w  = (const float*)d_in[20];
    const float* fc1_b  = (const float*)d_in[21];
    const float* fc2_w  = (const float*)d_in[22];
    const float* fc2_b  = (const float*)d_in[23];
    const float* fc3_w  = (const float*)d_in[24];
    const float* fc3_b  = (const float*)d_in[25];
    float* out = (float*)d_out;

    float *pxmiu, *pT1, *pT2, *ph3, *ph4, *px2, *pf1, *pf2;
    cudaGetSymbolAddress((void**)&pxmiu, g_xmiu);
    cudaGetSymbolAddress((void**)&pT1, g_T1);
    cudaGetSymbolAddress((void**)&pT2, g_T2);
    cudaGetSymbolAddress((void**)&ph3, g_h3);
    cudaGetSymbolAddress((void**)&ph4, g_h4);
    cudaGetSymbolAddress((void**)&px2, g_x2);
    cudaGetSymbolAddress((void**)&pf1, g_fc1o);
    cudaGetSymbolAddress((void**)&pf2, g_fc2o);

    // softmax first (independent of the data chain)
    k_softmax_all<<<52, 64>>>(and2_w, or2_w, and_w, or_w);

    k_conv1<<<dim3(C1, B), 256>>>(x, wave_w);
    k_bnfin<<<1, 512>>>(bn_g, bn_b);
    k_front<<<cdiv(B * C1 * L3, 256), 256>>>(miu_ap, miu_bp, miu_an, miu_bn);

    k_ae<0><<<dim3(3, B), 256>>>(pxmiu, ae_w1, ae_b1, pT1);
    k_ae<1><<<dim3(2, B), 256>>>(pT1, ae_w2, ae_b2, pT2);
    k_ae<2><<<dim3(2, B), 256>>>(pT2, ae_w3, ae_b3, ph3);
    k_ae<3><<<dim3(6, B), 128>>>(ph3, ae_w4, ae_b4, ph4);

    k_seg<<<cdiv(B * CM * LI, 256), 256>>>();

    k_logic1<<<dim3(cdiv(B * LU, 128), 2), 128>>>();
    k_logic2<<<cdiv(B * LU, 128), 128>>>();

    k_gemm64<<<dim3(1024 / 64, (B * 12) / 64), 256>>>(px2, fc1_w, fc1_b, pf1, B * 12, 1024, LU, 1);
    k_gemm64<<<dim3(256 / 64, (B * 12) / 64), 256>>>(pf1, fc2_w, fc2_b, pf2, B * 12, 256, 1024, 1);
    k_fc3<<<cdiv(B * 12 * 10, 256), 256>>>(pf2, fc3_w, fc3_b, out);

    (void)in_sizes; (void)n_in; (void)out_size;
}

// round 4
// speedup vs baseline: 2.6792x; 1.1826x over previous
#include <cuda_runtime.h>
#include <math.h>

#define B    128
#define C1   16
#define L0   719
#define L1   688
#define L3   171
#define CM   32
#define L9   174
#define CI   160
#define LI   171
#define LU   170
#define EPSL 1e-6f
#define LOGEPS  (-13.815511f)      /* log(1e-6) */
#define LOG1PE  (9.9999905e-07f)   /* log(1+1e-6) */

// ---------------- scratch ----------------
__device__ float  g_conv1[B*C1*L1];
__device__ double g_bns[C1*B*2];
__device__ float  g_xmiu[B*CM*L3];     // channel-first
__device__ float  g_h4[B*32*L9];       // channel-first
__device__ float  g_x1[B*40*LU];       // logic1 outputs only
__device__ float  g_x2[B*12*LU];
__device__ float  g_fc1o[B*12*1024];
__device__ float  g_fc2o[B*12*256];
__device__ float  g_wn_and2[20*CI*2];
__device__ float  g_wn_or2 [20*CI*2];
__device__ float  g_wn_and [6*200*2];
__device__ float  g_wn_or  [6*200*2];
__device__ float  g_s1_and[6];
__device__ float  g_s1_or[6];

static inline int cdiv(int a, int b) { return (a + b - 1) / b; }

__device__ __forceinline__ float sigfast(float z) {
    return __fdividef(1.0f, 1.0f + __expf(-z));
}
__device__ __forceinline__ int binof(float wv) {
    return (wv >= 0.8f) ? 4 : (wv >= 0.6f) ? 3 : (wv >= 0.4f) ? 2 : (wv >= 0.2f) ? 1 : 0;
}

// ---------------- conv1 + BN partial stats ----------------
__global__ void k_conv1(const float* __restrict__ x, const float* __restrict__ w) {
    int c = blockIdx.x, b = blockIdx.y;
    int tid = threadIdx.x;
    double ls = 0.0, ls2 = 0.0;
    if (tid < L1 / 4) {
        int t = tid * 4;
        const float* xr = x + b * L0 + t;
        const float* wr = w + c * 32;
        float s0 = 0.f, s1 = 0.f, s2 = 0.f, s3 = 0.f;
        float x0 = xr[0], x1v = xr[1], x2v = xr[2];
#pragma unroll
        for (int k = 0; k < 32; k++) {
            float xn = xr[k + 3];
            float wv = __ldg(wr + k);
            s0 = fmaf(x0, wv, s0);
            s1 = fmaf(x1v, wv, s1);
            s2 = fmaf(x2v, wv, s2);
            s3 = fmaf(xn, wv, s3);
            x0 = x1v; x1v = x2v; x2v = xn;
        }
        float* out = &g_conv1[(b * C1 + c) * L1 + t];
        out[0] = s0; out[1] = s1; out[2] = s2; out[3] = s3;
        ls = (double)s0 + (double)s1 + (double)s2 + (double)s3;
        ls2 = (double)s0*s0 + (double)s1*s1 + (double)s2*s2 + (double)s3*s3;
    }
    __shared__ double sh[256], sh2[256];
    sh[tid] = ls; sh2[tid] = ls2;
    __syncthreads();
    for (int st = 128; st > 0; st >>= 1) {
        if (tid < st) { sh[tid] += sh[tid + st]; sh2[tid] += sh2[tid + st]; }
        __syncthreads();
    }
    if (tid == 0) {
        g_bns[(c * B + b) * 2 + 0] = sh[0];
        g_bns[(c * B + b) * 2 + 1] = sh2[0];
    }
}

// ---------------- fused bnfin + bn + relu + pool + miu + pool ----------------
// grid (C1, B), 192 threads
__global__ void k_front(const float* __restrict__ gg, const float* __restrict__ bb,
                        const float* __restrict__ ap, const float* __restrict__ bp,
                        const float* __restrict__ an, const float* __restrict__ bn) {
    int c = blockIdx.x, b = blockIdx.y;
    int tid = threadIdx.x;
    __shared__ double rs[4], rs2[4];
    __shared__ float ssc, ssh;
    if (tid < 128) {
        double s = g_bns[(c * B + tid) * 2 + 0];
        double q = g_bns[(c * B + tid) * 2 + 1];
#pragma unroll
        for (int o = 16; o > 0; o >>= 1) {
            s += __shfl_down_sync(0xffffffff, s, o);
            q += __shfl_down_sync(0xffffffff, q, o);
        }
        if ((tid & 31) == 0) { rs[tid >> 5] = s; rs2[tid >> 5] = q; }
    }
    __syncthreads();
    if (tid == 0) {
        double s = rs[0] + rs[1] + rs[2] + rs[3];
        double q = rs2[0] + rs2[1] + rs2[2] + rs2[3];
        double n = (double)(B * L1);
        double mean = s / n;
        double var = q / n - mean * mean;
        float inv = rsqrtf((float)var + 1e-5f);
        float sc = gg[c] * inv;
        ssc = sc;
        ssh = bb[c] - (float)mean * sc;
    }
    __syncthreads();
    if (tid >= L3) return;
    int l = tid;
    const float* cr = &g_conv1[(b * C1 + c) * L1 + 4 * l];
    float sc = ssc, sh = ssh;
    float a[7];
#pragma unroll
    for (int i = 0; i < 7; i++) a[i] = fmaxf(0.f, fmaf(cr[i], sc, sh));
    float xf0 = fmaxf(fmaxf(a[0], a[1]), a[2]);
    float xf1 = fmaxf(fmaxf(a[2], a[3]), a[4]);
    float xf2 = fmaxf(fmaxf(a[4], a[5]), a[6]);
    float a_p = ap[c], b_p = bp[c], a_n = an[c], b_n = bn[c];
    float mp = fmaxf(fmaxf(sigfast(a_p * (xf0 - b_p)), sigfast(a_p * (xf1 - b_p))),
                     sigfast(a_p * (xf2 - b_p)));
    float mn = fmaxf(fmaxf(sigfast(-a_n * (xf0 - b_n)), sigfast(-a_n * (xf1 - b_n))),
                     sigfast(-a_n * (xf2 - b_n)));
    g_xmiu[(b * CM + c) * L3 + l] = mp;
    g_xmiu[(b * CM + 16 + c) * L3 + l] = mn;
}

// ---------------- entire autoencoder in one kernel (1 block / batch) ----------------
// dynamic smem: sW 6144 | sA 5709 | sB 11115  (= 91.9KB)
__global__ void k_ae_all(const float* __restrict__ xmiu,
                         const float* __restrict__ w1, const float* __restrict__ b1,
                         const float* __restrict__ w2, const float* __restrict__ b2,
                         const float* __restrict__ w3, const float* __restrict__ b3,
                         const float* __restrict__ w4, const float* __restrict__ b4,
                         float* __restrict__ h4g) {
    extern __shared__ float sm[];
    float* sW = sm;
    float* sA = sm + 6144;
    float* sB = sm + 6144 + 5709;
    const int OFF2 = 8192;
    int b = blockIdx.x, tid = threadIdx.x;

    // S0: W1 + x staging (rows 0..172, stride 33)
    for (int i = tid; i < 6144; i += 256) {
        int oc = i / 96, r = i % 96, ic = r / 3, kw = r % 3;
        sW[(kw * 32 + ic) * 64 + oc] = w1[i];
    }
    for (int i = tid; i < 173 * 32; i += 256) {
        int r = i / 32, ic = i % 32, l = r - 1;
        sA[r * 33 + ic] = (l >= 0 && l < L3) ? xmiu[(b * 32 + ic) * L3 + l] : 0.f;
    }
    __syncthreads();

    // S1: conv1(k3,pad1)+tanh -> T1 in sB (171 rows, stride 65)
    for (int it = tid; it < 688; it += 256) {
        int og = it % 16, lg = it / 16, l0 = lg * 4;
        float acc[4][4] = {};
#pragma unroll
        for (int kw = 0; kw < 3; kw++)
            for (int ic = 0; ic < 32; ic++) {
                float4 wv = *reinterpret_cast<const float4*>(&sW[(kw * 32 + ic) * 64 + og * 4]);
#pragma unroll
                for (int i = 0; i < 4; i++) {
                    float a = sA[min(l0 + i + kw, 172) * 33 + ic];
                    acc[i][0] = fmaf(a, wv.x, acc[i][0]);
                    acc[i][1] = fmaf(a, wv.y, acc[i][1]);
                    acc[i][2] = fmaf(a, wv.z, acc[i][2]);
                    acc[i][3] = fmaf(a, wv.w, acc[i][3]);
                }
            }
#pragma unroll
        for (int i = 0; i < 4; i++) {
            int l = l0 + i;
            if (l < L3)
#pragma unroll
                for (int j = 0; j < 4; j++)
                    sB[l * 65 + og * 4 + j] = tanhf(acc[i][j] + __ldg(b1 + og * 4 + j));
        }
    }
    __syncthreads();

    // S2: W2 + pool(3,2) T1 -> h1 in sA (87 rows incl pads, stride 65)
    for (int i = tid; i < 6144; i += 256) {
        int oc = i / 192, r = i % 192, ic = r / 3, kw = r % 3;
        sW[(kw * 64 + ic) * 32 + oc] = w2[i];
    }
    for (int i = tid; i < 87 * 64; i += 256) {
        int r = i / 64, ic = i % 64, p = r - 1;
        float v = 0.f;
        if (p >= 0 && p < 85) {
            const float* t1 = &sB[(2 * p) * 65 + ic];
            v = fmaxf(fmaxf(t1[0], t1[65]), t1[130]);
        }
        sA[r * 65 + ic] = v;
    }
    __syncthreads();

    // S3: conv2(k3,pad1)+relu -> T2 in sB rows 0..84 (stride 33)
    for (int it = tid; it < 176; it += 256) {
        int og = it % 8, pg = it / 8, p0 = pg * 4;
        float acc[4][4] = {};
#pragma unroll
        for (int kw = 0; kw < 3; kw++)
            for (int ic = 0; ic < 64; ic++) {
                float4 wv = *reinterpret_cast<const float4*>(&sW[(kw * 64 + ic) * 32 + og * 4]);
#pragma unroll
                for (int i = 0; i < 4; i++) {
                    float a = sA[min(p0 + i + kw, 86) * 65 + ic];
                    acc[i][0] = fmaf(a, wv.x, acc[i][0]);
                    acc[i][1] = fmaf(a, wv.y, acc[i][1]);
                    acc[i][2] = fmaf(a, wv.z, acc[i][2]);
                    acc[i][3] = fmaf(a, wv.w, acc[i][3]);
                }
            }
#pragma unroll
        for (int i = 0; i < 4; i++) {
            int p = p0 + i;
            if (p < 85)
#pragma unroll
                for (int j = 0; j < 4; j++)
                    sB[p * 33 + og * 4 + j] = fmaxf(0.f, acc[i][j] + __ldg(b2 + og * 4 + j));
        }
    }
    __syncthreads();

    // S4: W3 + pool(3,2) T2 -> h2 at sB[OFF2] (42 rows, stride 33)
    for (int i = tid; i < 6144; i += 256) {
        int oc = i / 96, r = i % 96, ic = r / 3, kw = r % 3;
        sW[(kw * 32 + ic) * 64 + oc] = w3[i];
    }
    for (int i = tid; i < 42 * 32; i += 256) {
        int j = i / 32, ic = i % 32;
        const float* t2 = &sB[(2 * j) * 33 + ic];
        sB[OFF2 + j * 33 + ic] = fmaxf(fmaxf(t2[0], t2[33]), t2[66]);
    }
    __syncthreads();

    // S5: up2(h2) -> conv3(k3,pad2)+tanh -> h3 in sA (86 rows, stride 65)
    for (int it = tid; it < 352; it += 256) {
        int og = it % 16, tg = it / 16, t0 = tg * 4;
        float acc[4][4] = {};
#pragma unroll
        for (int kw = 0; kw < 3; kw++)
            for (int ic = 0; ic < 32; ic++) {
                float4 wv = *reinterpret_cast<const float4*>(&sW[(kw * 32 + ic) * 64 + og * 4]);
#pragma unroll
                for (int i = 0; i < 4; i++) {
                    int u = t0 + i - 2 + kw;
                    float a = 0.f;
                    if (u >= 0 && u < 84) {
                        int j = u >> 1;
                        int ja, jb; float wa, wb;
                        if (u & 1) { ja = j; jb = (j < 41) ? j + 1 : 41; wa = 0.75f; wb = 0.25f; }
                        else       { ja = (j > 0) ? j - 1 : 0; jb = j;  wa = 0.25f; wb = 0.75f; }
                        a = wa * sB[OFF2 + ja * 33 + ic] + wb * sB[OFF2 + jb * 33 + ic];
                    }
                    acc[i][0] = fmaf(a, wv.x, acc[i][0]);
                    acc[i][1] = fmaf(a, wv.y, acc[i][1]);
                    acc[i][2] = fmaf(a, wv.z, acc[i][2]);
                    acc[i][3] = fmaf(a, wv.w, acc[i][3]);
                }
            }
#pragma unroll
        for (int i = 0; i < 4; i++) {
            int t = t0 + i;
            if (t < 86)
#pragma unroll
                for (int j = 0; j < 4; j++)
                    sA[t * 65 + og * 4 + j] = tanhf(acc[i][j] + __ldg(b3 + og * 4 + j));
        }
    }
    __syncthreads();

    // S6: W4
    for (int i = tid; i < 6144; i += 256) {
        int oc = i / 192, r = i % 192, ic = r / 3, kw = r % 3;
        sW[(kw * 64 + ic) * 32 + oc] = w4[i];
    }
    __syncthreads();

    // S7: up2(h3) -> conv4(k3,pad2)+sigmoid -> h4 GLOBAL channel-first
    for (int it = tid; it < 352; it += 256) {
        int og = it % 8, tg = it / 8, t0 = tg * 4;
        float acc[4][4] = {};
#pragma unroll
        for (int kw = 0; kw < 3; kw++)
            for (int ic = 0; ic < 64; ic++) {
                float4 wv = *reinterpret_cast<const float4*>(&sW[(kw * 64 + ic) * 32 + og * 4]);
#pragma unroll
                for (int i = 0; i < 4; i++) {
                    int u = t0 + i - 2 + kw;
                    float a = 0.f;
                    if (u >= 0 && u < 172) {
                        int j = u >> 1;
                        int ja, jb; float wa, wb;
                        if (u & 1) { ja = j; jb = (j < 85) ? j + 1 : 85; wa = 0.75f; wb = 0.25f; }
                        else       { ja = (j > 0) ? j - 1 : 0; jb = j;  wa = 0.25f; wb = 0.75f; }
                        a = wa * sA[ja * 65 + ic] + wb * sA[jb * 65 + ic];
                    }
                    acc[i][0] = fmaf(a, wv.x, acc[i][0]);
                    acc[i][1] = fmaf(a, wv.y, acc[i][1]);
                    acc[i][2] = fmaf(a, wv.z, acc[i][2]);
                    acc[i][3] = fmaf(a, wv.w, acc[i][3]);
                }
            }
#pragma unroll
        for (int i = 0; i < 4; i++) {
            int t = t0 + i;
            if (t < L9)
#pragma unroll
                for (int j = 0; j < 4; j++)
                    h4g[(b * 32 + og * 4 + j) * L9 + t] =
                        sigfast(acc[i][j] + __ldg(b4 + og * 4 + j));
        }
    }
}

// ---------------- softmax of logic weights + odd-tap sums ----------------
__global__ void k_softmax_all(const float* __restrict__ and2_w, const float* __restrict__ or2_w,
                              const float* __restrict__ and_w, const float* __restrict__ or_w) {
    int blk = blockIdx.x;
    const float* src; float* dst; int sz, o; float* s1dst = nullptr;
    if (blk < 20)      { src = and2_w; dst = g_wn_and2; sz = 320; o = blk; }
    else if (blk < 40) { src = or2_w;  dst = g_wn_or2;  sz = 320; o = blk - 20; }
    else if (blk < 46) { src = and_w;  dst = g_wn_and;  sz = 400; o = blk - 40; s1dst = g_s1_and; }
    else               { src = or_w;   dst = g_wn_or;   sz = 400; o = blk - 46; s1dst = g_s1_or; }
    const float* row = src + o * sz;
    int tid = threadIdx.x;
    __shared__ float red[64];
    float mx = -INFINITY;
    for (int i = tid; i < sz; i += 64) mx = fmaxf(mx, row[i]);
    red[tid] = mx; __syncthreads();
    for (int s = 32; s > 0; s >>= 1) { if (tid < s) red[tid] = fmaxf(red[tid], red[tid + s]); __syncthreads(); }
    mx = red[0]; __syncthreads();
    float sm = 0.f;
    for (int i = tid; i < sz; i += 64) sm += expf(row[i] - mx);
    red[tid] = sm; __syncthreads();
    for (int s = 32; s > 0; s >>= 1) { if (tid < s) red[tid] += red[tid + s]; __syncthreads(); }
    sm = red[0]; __syncthreads();
    float sodd = 0.f;
    for (int i = tid; i < sz; i += 64) {
        float v = expf(row[i] - mx) / sm;
        dst[o * sz + i] = v;
        if (i & 1) sodd += v;
    }
    if (s1dst) {
        red[tid] = sodd; __syncthreads();
        for (int s = 32; s > 0; s >>= 1) { if (tid < s) red[tid] += red[tid + s]; __syncthreads(); }
        if (tid == 0) s1dst[o] = red[0];
    }
}

// ---------------- logic layer 1 (seg inline, sparse bins) ----------------
// grid (cdiv(B*LU,128), 2); type 0 = and, 1 = or
__global__ void k_logic1() {
    __shared__ float2 sw2[20 * CI];  // [o][ch] -> (tap0, tap1)
    int tid = threadIdx.x;
    int type = blockIdx.y;
    const float2* wsrc = reinterpret_cast<const float2*>(type == 0 ? g_wn_and2 : g_wn_or2);
    for (int i = tid; i < 20 * CI; i += 128) sw2[i] = wsrc[i];
    __syncthreads();
    int idx = blockIdx.x * 128 + tid;
    if (idx >= B * LU) return;
    int t = idx % LU, b = idx / LU;
    float base = (type == 0) ? LOGEPS : LOG1PE;
    float acc[20];
#pragma unroll
    for (int o = 0; o < 20; o++) acc[o] = base;
    for (int c = 0; c < 32; c++) {
        const float* h4p = &g_h4[(b * 32 + c) * L9 + t];
        float h0 = h4p[0], h1 = h4p[1], h2 = h4p[2], h3 = h4p[3], h4v = h4p[4];
        float wv0 = fmaxf(fmaxf(h0, h1), fmaxf(h2, h3));
        float wv1 = fmaxf(fmaxf(h1, h2), fmaxf(h3, h4v));
        const float* xmp = &g_xmiu[(b * 32 + c) * L3 + t];
        float p0 = wv0 * xmp[0], p1 = wv1 * xmp[1];
        int ch0 = binof(wv0) * 32 + c;
        int ch1 = binof(wv1) * 32 + c;
        float d0, d1;
        if (type == 0) {
            d0 = __logf(p0 + EPSL) - LOGEPS;
            d1 = __logf(p1 + EPSL) - LOGEPS;
        } else {
            d0 = __logf(1.0f - p0 + EPSL) - LOG1PE;
            d1 = __logf(1.0f - p1 + EPSL) - LOG1PE;
        }
#pragma unroll
        for (int o = 0; o < 20; o++) {
            acc[o] = fmaf(sw2[o * CI + ch0].x, d0, acc[o]);
            acc[o] = fmaf(sw2[o * CI + ch1].y, d1, acc[o]);
        }
    }
    float* x1 = &g_x1[(b * 40 + (type == 0 ? 0 : 20)) * LU + t];
    if (type == 0) {
#pragma unroll
        for (int o = 0; o < 20; o++) x1[o * LU] = fmaxf(0.f, __expf(acc[o]));
    } else {
#pragma unroll
        for (int o = 0; o < 20; o++) x1[o * LU] = fmaxf(0.f, 1.0f - __expf(acc[o]));
    }
}

// ---------------- logic layer 2 (until inline, sparse bins) ----------------
__global__ void k_logic2() {
    __shared__ float2 swa2[6 * 200];
    __shared__ float2 swo2[6 * 200];
    int tid = threadIdx.x;
    const float2* wa = reinterpret_cast<const float2*>(g_wn_and);
    const float2* wo = reinterpret_cast<const float2*>(g_wn_or);
    for (int i = tid; i < 6 * 200; i += 128) { swa2[i] = wa[i]; swo2[i] = wo[i]; }
    __syncthreads();
    int idx = blockIdx.x * 128 + tid;
    if (idx >= B * LU) return;
    int t = idx % LU, b = idx / LU;
    bool hasL = (t > 0);
    float sa[6], so[6];
#pragma unroll
    for (int o = 0; o < 6; o++) {
        float fa = hasL ? 1.0f : g_s1_and[o];
        float fo = hasL ? 1.0f : g_s1_or[o];
        sa[o] = LOGEPS * fa;
        so[o] = LOG1PE * fo;
    }
    // dense channels 0..39 from x1
    const float* xp = &g_x1[b * 40 * LU + t];
    for (int c = 0; c < 40; c++) {
        float v1 = xp[c * LU];
        float cv1 = fminf(fmaxf(v1, 0.f), 1.f);
        float d1p = __logf(cv1 + EPSL) - LOGEPS;
        float d1q = __logf(1.0f - cv1 + EPSL) - LOG1PE;
        float d0p = 0.f, d0q = 0.f;
        if (hasL) {
            float v0 = xp[c * LU - 1];
            float cv0 = fminf(fmaxf(v0, 0.f), 1.f);
            d0p = __logf(cv0 + EPSL) - LOGEPS;
            d0q = __logf(1.0f - cv0 + EPSL) - LOG1PE;
        }
#pragma unroll
        for (int o = 0; o < 6; o++) {
            float2 a2 = swa2[o * 200 + c];
            float2 o2 = swo2[o * 200 + c];
            sa[o] = fmaf(a2.y, d1p, sa[o]);
            so[o] = fmaf(o2.y, d1q, so[o]);
            if (hasL) {
                sa[o] = fmaf(a2.x, d0p, sa[o]);
                so[o] = fmaf(o2.x, d0q, so[o]);
            }
        }
    }
    // until channels (40 + k*32 + c), recomputed inline
    for (int c = 0; c < 32; c++) {
        const float* h4p = &g_h4[(b * 32 + c) * L9 + t];
        const float* xmp = &g_xmiu[(b * 32 + c) * L3 + t];
        float h0 = h4p[0], h1 = h4p[1], h2 = h4p[2], h3 = h4p[3], h4v = h4p[4];
        float wv0 = fmaxf(fmaxf(h0, h1), fmaxf(h2, h3));        // pos t
        float wv1 = fmaxf(fmaxf(h1, h2), fmaxf(h3, h4v));       // pos t+1
        float p_0 = wv0 * xmp[0], p_1 = wv1 * xmp[1];
        int k0 = binof(wv0), k1 = binof(wv1);
        // tap1 = until at position t: active iff k0==k1
        if (k0 == k1) {
            int ch = 40 + k0 * 32 + c;
            float u = fminf(p_0, p_1);
            float dp = __logf(u + EPSL) - LOGEPS;
            float dq = __logf(1.0f - u + EPSL) - LOG1PE;
#pragma unroll
            for (int o = 0; o < 6; o++) {
                sa[o] = fmaf(swa2[o * 200 + ch].y, dp, sa[o]);
                so[o] = fmaf(swo2[o * 200 + ch].y, dq, so[o]);
            }
        }
        // tap0 = until at position t-1: active iff km1==k0
        if (hasL) {
            float hm1 = h4p[-1];
            float wvm = fmaxf(fmaxf(hm1, h0), fmaxf(h1, h2));
            float p_m = wvm * xmp[-1];
            int km = binof(wvm);
            if (km == k0) {
                int ch = 40 + km * 32 + c;
                float u = fminf(p_m, p_0);
                float dp = __logf(u + EPSL) - LOGEPS;
                float dq = __logf(1.0f - u + EPSL) - LOG1PE;
#pragma unroll
                for (int o = 0; o < 6; o++) {
                    sa[o] = fmaf(swa2[o * 200 + ch].x, dp, sa[o]);
                    so[o] = fmaf(swo2[o * 200 + ch].x, dq, so[o]);
                }
            }
        }
    }
#pragma unroll
    for (int o = 0; o < 6; o++) {
        g_x2[(b * 12 + o) * LU + t] = fmaxf(0.f, __expf(sa[o]));
        g_x2[(b * 12 + 6 + o) * LU + t] = fmaxf(0.f, 1.0f - __expf(so[o]));
    }
}

// ---------------- FC GEMM ----------------
__global__ void k_gemm64(const float* __restrict__ A, const float* __restrict__ W,
                         const float* __restrict__ bias, float* __restrict__ C,
                         int M, int N, int K, int relu) {
    __shared__ float As[16][68];
    __shared__ float Bs[16][68];
    int tid = threadIdx.x;
    int tx = tid % 16, ty = tid / 16;
    int m0 = blockIdx.y * 64, n0 = blockIdx.x * 64;
    float acc[4][4] = {};
    for (int k0 = 0; k0 < K; k0 += 16) {
        int gk = k0 + tx;
        bool kv = (gk < K);
#pragma unroll
        for (int i = 0; i < 4; i++) {
            int r = ty + i * 16;
            int gm = m0 + r;
            As[tx][r] = (kv && gm < M) ? A[gm * K + gk] : 0.f;
            int gn = n0 + r;
            Bs[tx][r] = (kv && gn < N) ? W[gn * K + gk] : 0.f;
        }
        __syncthreads();
#pragma unroll
        for (int kk = 0; kk < 16; kk++) {
            float4 a = *reinterpret_cast<const float4*>(&As[kk][ty * 4]);
            float4 bq = *reinterpret_cast<const float4*>(&Bs[kk][tx * 4]);
            float av[4] = {a.x, a.y, a.z, a.w};
            float bv[4] = {bq.x, bq.y, bq.z, bq.w};
#pragma unroll
            for (int i = 0; i < 4; i++)
#pragma unroll
                for (int j = 0; j < 4; j++)
                    acc[i][j] = fmaf(av[i], bv[j], acc[i][j]);
        }
        __syncthreads();
    }
#pragma unroll
    for (int i = 0; i < 4; i++) {
        int gm = m0 + ty * 4 + i;
        if (gm >= M) continue;
#pragma unroll
        for (int j = 0; j < 4; j++) {
            int gn = n0 + tx * 4 + j;
            if (gn >= N) continue;
            float v = acc[i][j] + bias[gn];
            if (relu) v = fmaxf(v, 0.f);
            C[gm * N + gn] = v;
        }
    }
}

__global__ void k_fc3(const float* __restrict__ A, const float* __restrict__ W,
                      const float* __restrict__ bias, float* __restrict__ C) {
    int idx = blockIdx.x * blockDim.x + threadIdx.x;
    if (idx >= B * 12 * 10) return;
    int m = idx / 10, n = idx % 10;
    float s = bias[n];
    const float* a = A + m * 256;
    const float* w = W + n * 256;
#pragma unroll 8
    for (int k = 0; k < 256; k++) s = fmaf(a[k], __ldg(w + k), s);
    C[idx] = s;
}

// ---------------- launcher ----------------

extern "C" void kernel_launch(void* const* d_in, const int* in_sizes, int n_in,
                              void* d_out, int out_size) {
    const float* x      = (const float*)d_in[0];
    const float* wave_w = (const float*)d_in[1];
    const float* bn_g   = (const float*)d_in[2];
    const float* bn_b   = (const float*)d_in[3];
    const float* miu_ap = (const float*)d_in[4];
    const float* miu_bp = (const float*)d_in[5];
    const float* miu_an = (const float*)d_in[6];
    const float* miu_bn = (const float*)d_in[7];
    const float* ae_w1  = (const float*)d_in[8];
    const float* ae_b1  = (const float*)d_in[9];
    const float* ae_w2  = (const float*)d_in[10];
    const float* ae_b2  = (const float*)d_in[11];
    const float* ae_w3  = (const float*)d_in[12];
    const float* ae_b3  = (const float*)d_in[13];
    const float* ae_w4  = (const float*)d_in[14];
    const float* ae_b4  = (const float*)d_in[15];
    const float* and2_w = (const float*)d_in[16];
    const float* or2_w  = (const float*)d_in[17];
    const float* and_w  = (const float*)d_in[18];
    const float* or_w   = (const float*)d_in[19];
    const float* fc1_w  = (const float*)d_in[20];
    const float* fc1_b  = (const float*)d_in[21];
    const float* fc2_w  = (const float*)d_in[22];
    const float* fc2_b  = (const float*)d_in[23];
    const float* fc3_w  = (const float*)d_in[24];
    const float* fc3_b  = (const float*)d_in[25];
    float* out = (float*)d_out;

    float *pxmiu, *ph4, *px2, *pf1, *pf2;
    cudaGetSymbolAddress((void**)&pxmiu, g_xmiu);
    cudaGetSymbolAddress((void**)&ph4, g_h4);
    cudaGetSymbolAddress((void**)&px2, g_x2);
    cudaGetSymbolAddress((void**)&pf1, g_fc1o);
    cudaGetSymbolAddress((void**)&pf2, g_fc2o);

    const int AE_SMEM = (6144 + 5709 + 11115) * 4;
    cudaFuncSetAttribute(k_ae_all, cudaFuncAttributeMaxDynamicSharedMemorySize, AE_SMEM);

    k_softmax_all<<<52, 64>>>(and2_w, or2_w, and_w, or_w);
    k_conv1<<<dim3(C1, B), 256>>>(x, wave_w);
    k_front<<<dim3(C1, B), 192>>>(bn_g, bn_b, miu_ap, miu_bp, miu_an, miu_bn);
    k_ae_all<<<B, 256, AE_SMEM>>>(pxmiu, ae_w1, ae_b1, ae_w2, ae_b2,
                                  ae_w3, ae_b3, ae_w4, ae_b4, ph4);
    k_logic1<<<dim3(cdiv(B * LU, 128), 2), 128>>>();
    k_logic2<<<cdiv(B * LU, 128), 128>>>();
    k_gemm64<<<dim3(1024 / 64, (B * 12) / 64), 256>>>(px2, fc1_w, fc1_b, pf1, B * 12, 1024, LU, 1);
    k_gemm64<<<dim3(256 / 64, (B * 12) / 64), 256>>>(pf1, fc2_w, fc2_b, pf2, B * 12, 256, 1024, 1);
    k_fc3<<<cdiv(B * 12 * 10, 256), 256>>>(pf2, fc3_w, fc3_b, out);

    (void)in_sizes; (void)n_in; (void)out_size;
}